// round 1
// baseline (speedup 1.0000x reference)
#include <cuda_runtime.h>
#include <cstddef>

#define NB 4
#define SEQL 2048
#define EMB 1024

// Scratch (static __device__ arrays are allowed; no allocation at runtime)
__device__ float g_v[NB * SEQL * EMB];     // projected V   (32 MB)
__device__ float g_k[NB * SEQL * EMB];     // projected K   (32 MB)
__device__ float g_q[NB * SEQL * EMB];     // projected Q   (32 MB)
__device__ float g_e[(size_t)NB * SEQL * SEQL]; // energy / attn (64 MB)
__device__ float g_o[NB * SEQL * EMB];     // attn @ V      (32 MB)

// ---------------------------------------------------------------------------
// Tiled SGEMM:  C[M,N] = A[M,K] * op(B)  (+ bias)
//   TRANSB=true : B is [N,K] row-major (C = A * B^T)  -- used for X*W^T, Q*K^T
//   TRANSB=false: B is [K,N] row-major (C = A * B)    -- used for P*V
// Batched via blockIdx.z with element strides sA/sB/sC.
// Tiles: 64x64x16, 256 threads (16x16), 4x4 accumulators per thread.
// Requires M%64==0, N%64==0, K%16==0 (true for all shapes here).
// ---------------------------------------------------------------------------
template <bool TRANSB, bool BIAS>
__global__ __launch_bounds__(256)
void gemm_kernel(const float* __restrict__ A, const float* __restrict__ B,
                 const float* __restrict__ bias, float* __restrict__ C,
                 int M, int N, int K, size_t sA, size_t sB, size_t sC)
{
    __shared__ float As[16][64];
    __shared__ float Bs[16][64];

    const int tx = threadIdx.x;            // N dim (0..15)
    const int ty = threadIdx.y;            // M dim (0..15)
    const int tid = ty * 16 + tx;
    const int m0 = blockIdx.y * 64;
    const int n0 = blockIdx.x * 64;

    A += (size_t)blockIdx.z * sA;
    B += (size_t)blockIdx.z * sB;
    C += (size_t)blockIdx.z * sC;

    float acc[4][4] = {};

    // A-load mapping (also B-load for TRANSB): one float4 per thread
    const int ar  = tid >> 2;          // 0..63 tile row
    const int ac4 = (tid & 3) * 4;     // 0,4,8,12 tile col (k)
    // B-load mapping for non-transposed B
    const int br  = tid >> 4;          // 0..15 tile row (k)
    const int bc4 = (tid & 15) * 4;    // 0..60 tile col (n)

    for (int k0 = 0; k0 < K; k0 += 16) {
        float4 av = *(const float4*)(A + (size_t)(m0 + ar) * K + k0 + ac4);
        As[ac4 + 0][ar] = av.x;
        As[ac4 + 1][ar] = av.y;
        As[ac4 + 2][ar] = av.z;
        As[ac4 + 3][ar] = av.w;

        if (TRANSB) {
            float4 bv = *(const float4*)(B + (size_t)(n0 + ar) * K + k0 + ac4);
            Bs[ac4 + 0][ar] = bv.x;
            Bs[ac4 + 1][ar] = bv.y;
            Bs[ac4 + 2][ar] = bv.z;
            Bs[ac4 + 3][ar] = bv.w;
        } else {
            float4 bv = *(const float4*)(B + (size_t)(k0 + br) * N + n0 + bc4);
            *(float4*)&Bs[br][bc4] = bv;
        }
        __syncthreads();

        #pragma unroll
        for (int kk = 0; kk < 16; kk++) {
            float4 a = *(const float4*)&As[kk][ty * 4];
            float4 b = *(const float4*)&Bs[kk][tx * 4];
            float ai[4] = {a.x, a.y, a.z, a.w};
            float bj[4] = {b.x, b.y, b.z, b.w};
            #pragma unroll
            for (int i = 0; i < 4; i++)
                #pragma unroll
                for (int j = 0; j < 4; j++)
                    acc[i][j] = fmaf(ai[i], bj[j], acc[i][j]);
        }
        __syncthreads();
    }

    #pragma unroll
    for (int i = 0; i < 4; i++) {
        const int row = m0 + ty * 4 + i;
        float4 r = make_float4(acc[i][0], acc[i][1], acc[i][2], acc[i][3]);
        if (BIAS) {
            const int n = n0 + tx * 4;
            r.x += bias[n + 0];
            r.y += bias[n + 1];
            r.z += bias[n + 2];
            r.w += bias[n + 3];
        }
        *(float4*)&C[(size_t)row * N + n0 + tx * 4] = r;
    }
}

// ---------------------------------------------------------------------------
// Masked softmax over each row of the energy matrix (in place).
// scaled = (mask==0 ? -1e20 : e) / sqrt(EMB);  p = softmax(scaled)
// One block (256 threads) per row of 2048; 8 elements per thread in registers.
// ---------------------------------------------------------------------------
__global__ __launch_bounds__(256)
void softmax_kernel(float* __restrict__ E, const int* __restrict__ mask)
{
    const int row = blockIdx.x;               // 0 .. NB*SEQL-1
    const int b = row / SEQL;
    const int q = row % SEQL;
    float* e = E + (size_t)row * SEQL;
    const int* m = mask + (size_t)b * SEQL * SEQL + (size_t)q * SEQL;

    const int t = threadIdx.x;
    float v[8];
    float mx = -3.4e38f;
    #pragma unroll
    for (int i = 0; i < 8; i++) {
        const int idx = t + i * 256;
        float x = e[idx];
        x = (m[idx] == 0) ? -1e20f : x;
        x *= 0.03125f;                       // 1/sqrt(1024)
        v[i] = x;
        mx = fmaxf(mx, x);
    }

    __shared__ float red[256];
    red[t] = mx;
    __syncthreads();
    #pragma unroll
    for (int s = 128; s > 0; s >>= 1) {
        if (t < s) red[t] = fmaxf(red[t], red[t + s]);
        __syncthreads();
    }
    mx = red[0];
    __syncthreads();

    float sum = 0.f;
    #pragma unroll
    for (int i = 0; i < 8; i++) {
        v[i] = expf(v[i] - mx);
        sum += v[i];
    }
    red[t] = sum;
    __syncthreads();
    #pragma unroll
    for (int s = 128; s > 0; s >>= 1) {
        if (t < s) red[t] += red[t + s];
        __syncthreads();
    }
    const float inv = 1.f / red[0];

    #pragma unroll
    for (int i = 0; i < 8; i++)
        e[t + i * 256] = v[i] * inv;
}

extern "C" void kernel_launch(void* const* d_in, const int* in_sizes, int n_in,
                              void* d_out, int out_size)
{
    const float* values = (const float*)d_in[0];
    const float* keys   = (const float*)d_in[1];
    const float* query  = (const float*)d_in[2];
    const int*   mask   = (const int*)  d_in[3];
    const float* Wv     = (const float*)d_in[4];
    const float* Wk     = (const float*)d_in[5];
    const float* Wq     = (const float*)d_in[6];
    const float* Wo     = (const float*)d_in[7];
    const float* bo     = (const float*)d_in[8];
    float* out = (float*)d_out;

    float *gv, *gk, *gq, *ge, *go;
    cudaGetSymbolAddress((void**)&gv, g_v);
    cudaGetSymbolAddress((void**)&gk, g_k);
    cudaGetSymbolAddress((void**)&gq, g_q);
    cudaGetSymbolAddress((void**)&ge, g_e);
    cudaGetSymbolAddress((void**)&go, g_o);

    const dim3 blk(16, 16);
    const int MQ = NB * SEQL;                 // 8192 rows for projections

    // Projections: X[8192,1024] * W[1024,1024]^T
    gemm_kernel<true, false><<<dim3(EMB / 64, MQ / 64, 1), blk>>>(
        values, Wv, nullptr, gv, MQ, EMB, EMB, 0, 0, 0);
    gemm_kernel<true, false><<<dim3(EMB / 64, MQ / 64, 1), blk>>>(
        keys, Wk, nullptr, gk, MQ, EMB, EMB, 0, 0, 0);
    gemm_kernel<true, false><<<dim3(EMB / 64, MQ / 64, 1), blk>>>(
        query, Wq, nullptr, gq, MQ, EMB, EMB, 0, 0, 0);

    // Energy: per-batch Q[2048,1024] * K[2048,1024]^T -> E[2048,2048]
    gemm_kernel<true, false><<<dim3(SEQL / 64, SEQL / 64, NB), blk>>>(
        gq, gk, nullptr, ge, SEQL, SEQL, EMB,
        (size_t)SEQL * EMB, (size_t)SEQL * EMB, (size_t)SEQL * SEQL);

    // Mask + scale + softmax (in place on E)
    softmax_kernel<<<NB * SEQL, 256>>>(ge, mask);

    // O = P[2048,2048] * V[2048,1024]   (B non-transposed)
    gemm_kernel<false, false><<<dim3(EMB / 64, SEQL / 64, NB), blk>>>(
        ge, gv, nullptr, go, SEQL, EMB, SEQL,
        (size_t)SEQL * SEQL, (size_t)SEQL * EMB, (size_t)SEQL * EMB);

    // Final: O[8192,1024] * Wo[1024,1024]^T + bo
    gemm_kernel<true, true><<<dim3(EMB / 64, MQ / 64, 1), blk>>>(
        go, Wo, bo, out, MQ, EMB, EMB, 0, 0, 0);
}

// round 3
// speedup vs baseline: 2.8007x; 2.8007x over previous
#include <cuda_runtime.h>
#include <cuda_fp16.h>
#include <cstdint>
#include <cstddef>

// ---------------------------------------------------------------------------
#define NBAT 4
#define SEQL 2048
#define EMB  1024
#define MQ   (NBAT * SEQL)   /* 8192 */

static constexpr size_t EX = (size_t)MQ * EMB;
static constexpr size_t EW = (size_t)EMB * EMB;
static constexpr size_t EP = (size_t)NBAT * SEQL * SEQL;

// Scratch (__device__ statics)
__device__ __half g_xvh[EX], g_xvl[EX];
__device__ __half g_xkh[EX], g_xkl[EX];
__device__ __half g_xqh[EX], g_xql[EX];
__device__ __half g_wvh[EW], g_wvl[EW];
__device__ __half g_wkh[EW], g_wkl[EW];
__device__ __half g_wqh[EW], g_wql[EW];
__device__ __half g_woh[EW], g_wol[EW];
__device__ __half g_qh[EX],  g_ql[EX];
__device__ __half g_kh[EX],  g_kl[EX];
__device__ __half g_vth[EX], g_vtl[EX];   // V projected, stored [b][emb][seq]
__device__ float  g_e[EP];
__device__ __half g_ph[EP],  g_pl[EP];
__device__ __half g_oh[EX],  g_ol[EX];

// ---------------------------------------------------------------------------
__device__ __forceinline__ uint32_t smem_u32(const void* p) {
    uint32_t a;
    asm("{ .reg .u64 t; cvta.to.shared.u64 t, %1; cvt.u32.u64 %0, t; }" : "=r"(a) : "l"(p));
    return a;
}
__device__ __forceinline__ void cp16(uint32_t s, const void* g) {
    asm volatile("cp.async.cg.shared.global [%0], [%1], 16;" :: "r"(s), "l"(g) : "memory");
}
#define CP_COMMIT() asm volatile("cp.async.commit_group;" ::: "memory")

__device__ __forceinline__ void ldsm4(uint32_t* r, uint32_t addr) {
    asm volatile("ldmatrix.sync.aligned.m8n8.x4.shared.b16 {%0,%1,%2,%3}, [%4];"
        : "=r"(r[0]), "=r"(r[1]), "=r"(r[2]), "=r"(r[3]) : "r"(addr));
}
__device__ __forceinline__ void mma16816(float* c, const uint32_t* a, const uint32_t* b) {
    asm volatile("mma.sync.aligned.m16n8k16.row.col.f32.f16.f16.f32 "
        "{%0,%1,%2,%3}, {%4,%5,%6,%7}, {%8,%9}, {%0,%1,%2,%3};"
        : "+f"(c[0]), "+f"(c[1]), "+f"(c[2]), "+f"(c[3])
        : "r"(a[0]), "r"(a[1]), "r"(a[2]), "r"(a[3]), "r"(b[0]), "r"(b[1]));
}

__device__ __forceinline__ void split2(float f0, float f1, uint32_t& hi, uint32_t& lo) {
    __half h0 = __float2half_rn(f0), h1 = __float2half_rn(f1);
    __half l0 = __float2half_rn(f0 - __half2float(h0));
    __half l1 = __float2half_rn(f1 - __half2float(h1));
    hi = (uint32_t)__half_as_ushort(h0) | ((uint32_t)__half_as_ushort(h1) << 16);
    lo = (uint32_t)__half_as_ushort(l0) | ((uint32_t)__half_as_ushort(l1) << 16);
}

// ---------------------------------------------------------------------------
// hi/lo-split HGEMM: C[M,N] = Ah*Bh^T + Ah*Bl^T + Al*Bh^T, fp32 accumulate.
// A,B K-major [rows][K]. Tile 128x128x32, 256 thr, 3-stage cp.async.
// smem rows padded to 80B (stride 40 halves) -> conflict-free ldmatrix.
// MODE: 0 fp32 | 1 split fp16 | 2 fp32+bias | 3 split fp16, N-dim batch-folded
//       (output index = (col/2048)*EMB*SEQL + row*SEQL + col%2048)
// ---------------------------------------------------------------------------
#define STAGES 3
#define TILE_B 10240               /* 128 rows * 80 B */
#define STG_B  (4 * TILE_B)        /* Ah, Al, Bh, Bl */
#define GEMM_SMEM (STAGES * STG_B) /* 122880 */

template <int MODE>
__global__ __launch_bounds__(256)
void hgemm(const __half* __restrict__ Ah, const __half* __restrict__ Al,
           const __half* __restrict__ Bh, const __half* __restrict__ Bl,
           int K, size_t sA, size_t sB,
           float* __restrict__ Cf, const float* __restrict__ bias,
           size_t sC, int Nc,
           __half* __restrict__ Ch, __half* __restrict__ Cl)
{
    extern __shared__ char smc[];
    const uint32_t sb = smem_u32(smc);
    const int tid = threadIdx.x, lane = tid & 31, wid = tid >> 5;
    const int m0 = blockIdx.y * 128, n0 = blockIdx.x * 128, b = blockIdx.z;
    const int nch = K >> 5;

    const __half* srcs[4];
    srcs[0] = Ah + (size_t)b * sA + (size_t)m0 * K;
    srcs[1] = Al + (size_t)b * sA + (size_t)m0 * K;
    srcs[2] = Bh + (size_t)b * sB + (size_t)n0 * K;
    srcs[3] = Bl + (size_t)b * sB + (size_t)n0 * K;

    // producer mapping: 8 x 16B chunks per thread per stage
    auto load_stage = [&](int s, int chunk) {
        const uint32_t dbase = sb + s * STG_B;
        const int k0 = chunk * 32;
        #pragma unroll
        for (int i = 0; i < 8; i++) {
            const int cid = tid + i * 256;
            const int tile = cid >> 9, r = (cid >> 2) & 127, seg = cid & 3;
            cp16(dbase + tile * TILE_B + r * 80 + seg * 16,
                 srcs[tile] + (size_t)r * K + k0 + seg * 8);
        }
    };

    #pragma unroll
    for (int s = 0; s < STAGES - 1; s++) { load_stage(s, s); CP_COMMIT(); }

    const int m0w = (wid >> 2) * 64, n0w = (wid & 3) * 32;
    const uint32_t aoff = (uint32_t)(m0w + (lane & 15)) * 80 + ((lane >> 4) * 16);
    const uint32_t boff = (uint32_t)(n0w + ((lane >> 4) & 1) * 8 + (lane & 7)) * 80
                        + (((lane >> 3) & 1) * 16);

    float acc[4][4][4];
    #pragma unroll
    for (int a = 0; a < 4; a++)
        #pragma unroll
        for (int c = 0; c < 4; c++)
            #pragma unroll
            for (int d = 0; d < 4; d++) acc[a][c][d] = 0.f;

    for (int c = 0; c < nch; c++) {
        asm volatile("cp.async.wait_group %0;" :: "n"(STAGES - 2));
        __syncthreads();
        if (c + STAGES - 1 < nch) load_stage((c + STAGES - 1) % STAGES, c + STAGES - 1);
        CP_COMMIT();

        const uint32_t st = sb + (c % STAGES) * STG_B;
        const uint32_t aH = st + aoff, aL = st + TILE_B + aoff;
        const uint32_t bH = st + 2 * TILE_B + boff, bL = st + 3 * TILE_B + boff;

        #pragma unroll
        for (int ks = 0; ks < 2; ks++) {
            uint32_t ah[4][4], al[4][4], bh[4][2], bl[4][2];
            #pragma unroll
            for (int mi = 0; mi < 4; mi++) {
                ldsm4(ah[mi], aH + mi * 1280 + ks * 32);
                ldsm4(al[mi], aL + mi * 1280 + ks * 32);
            }
            #pragma unroll
            for (int j = 0; j < 2; j++) {
                uint32_t t[4];
                ldsm4(t, bH + j * 1280 + ks * 32);
                bh[2*j][0] = t[0]; bh[2*j][1] = t[1];
                bh[2*j+1][0] = t[2]; bh[2*j+1][1] = t[3];
                ldsm4(t, bL + j * 1280 + ks * 32);
                bl[2*j][0] = t[0]; bl[2*j][1] = t[1];
                bl[2*j+1][0] = t[2]; bl[2*j+1][1] = t[3];
            }
            #pragma unroll
            for (int mi = 0; mi < 4; mi++)
                #pragma unroll
                for (int ni = 0; ni < 4; ni++) {
                    mma16816(acc[mi][ni], ah[mi], bh[ni]);
                    mma16816(acc[mi][ni], ah[mi], bl[ni]);
                    mma16816(acc[mi][ni], al[mi], bh[ni]);
                }
        }
    }

    // epilogue (register fragments -> global, no smem)
    const int fr = lane >> 2, fc = (lane & 3) * 2;
    #pragma unroll
    for (int mi = 0; mi < 4; mi++)
        #pragma unroll
        for (int ni = 0; ni < 4; ni++) {
            const int row = m0 + m0w + mi * 16 + fr;
            const int col = n0 + n0w + ni * 8 + fc;
            float* pc = acc[mi][ni];
            if (MODE == 0 || MODE == 2) {
                float2 v0 = make_float2(pc[0], pc[1]);
                float2 v1 = make_float2(pc[2], pc[3]);
                if (MODE == 2) {
                    const float b0v = bias[col], b1v = bias[col + 1];
                    v0.x += b0v; v0.y += b1v; v1.x += b0v; v1.y += b1v;
                }
                float* base = Cf + (size_t)b * sC;
                *(float2*)(base + (size_t)row * Nc + col) = v0;
                *(float2*)(base + (size_t)(row + 8) * Nc + col) = v1;
            } else if (MODE == 1) {
                uint32_t h0, l0, h1, l1;
                split2(pc[0], pc[1], h0, l0);
                split2(pc[2], pc[3], h1, l1);
                const size_t i0 = (size_t)b * sC + (size_t)row * Nc + col;
                const size_t i1 = (size_t)b * sC + (size_t)(row + 8) * Nc + col;
                *(uint32_t*)(Ch + i0) = h0; *(uint32_t*)(Cl + i0) = l0;
                *(uint32_t*)(Ch + i1) = h1; *(uint32_t*)(Cl + i1) = l1;
            } else {
                uint32_t h0, l0, h1, l1;
                split2(pc[0], pc[1], h0, l0);
                split2(pc[2], pc[3], h1, l1);
                const size_t bb = (size_t)(col >> 11) * ((size_t)EMB * SEQL);
                const size_t i0 = bb + (size_t)row * SEQL + (col & 2047);
                const size_t i1 = i0 + (size_t)8 * SEQL;
                *(uint32_t*)(Ch + i0) = h0; *(uint32_t*)(Cl + i0) = l0;
                *(uint32_t*)(Ch + i1) = h1; *(uint32_t*)(Cl + i1) = l1;
            }
        }
}

// ---------------------------------------------------------------------------
// fp32 -> fp16 hi/lo split
// ---------------------------------------------------------------------------
__global__ __launch_bounds__(256)
void split_kernel(const float* __restrict__ x, __half* __restrict__ h,
                  __half* __restrict__ l, int n4)
{
    int i = blockIdx.x * 256 + threadIdx.x;
    if (i >= n4) return;
    float4 v = ((const float4*)x)[i];
    uint32_t h0, l0, h1, l1;
    split2(v.x, v.y, h0, l0);
    split2(v.z, v.w, h1, l1);
    ((uint2*)h)[i] = make_uint2(h0, h1);
    ((uint2*)l)[i] = make_uint2(l0, l1);
}

// ---------------------------------------------------------------------------
// masked softmax on fp32 E, writing split-fp16 probabilities
// ---------------------------------------------------------------------------
__global__ __launch_bounds__(256)
void softmax_split(const float* __restrict__ E, const int* __restrict__ mask,
                   __half* __restrict__ Ph, __half* __restrict__ Pl)
{
    const int row = blockIdx.x;
    const int b = row >> 11;
    const float* e = E + (size_t)row * SEQL;
    const int* m = mask + (size_t)b * SEQL * SEQL + (size_t)(row & 2047) * SEQL;
    const int t = threadIdx.x;
    const int base = t * 8;

    float v[8];
    #pragma unroll
    for (int g = 0; g < 2; g++) {
        float4 ev = *(const float4*)(e + base + g * 4);
        int4 mv = *(const int4*)(m + base + g * 4);
        v[g*4+0] = ((mv.x == 0) ? -1e20f : ev.x) * 0.03125f;
        v[g*4+1] = ((mv.y == 0) ? -1e20f : ev.y) * 0.03125f;
        v[g*4+2] = ((mv.z == 0) ? -1e20f : ev.z) * 0.03125f;
        v[g*4+3] = ((mv.w == 0) ? -1e20f : ev.w) * 0.03125f;
    }
    float mx = -3.4e38f;
    #pragma unroll
    for (int i = 0; i < 8; i++) mx = fmaxf(mx, v[i]);

    __shared__ float red[256];
    red[t] = mx;
    __syncthreads();
    for (int s = 128; s > 0; s >>= 1) {
        if (t < s) red[t] = fmaxf(red[t], red[t + s]);
        __syncthreads();
    }
    mx = red[0];
    __syncthreads();

    float sum = 0.f;
    #pragma unroll
    for (int i = 0; i < 8; i++) { v[i] = __expf(v[i] - mx); sum += v[i]; }
    red[t] = sum;
    __syncthreads();
    for (int s = 128; s > 0; s >>= 1) {
        if (t < s) red[t] += red[t + s];
        __syncthreads();
    }
    const float inv = 1.f / red[0];

    uint32_t hv[4], lv[4];
    #pragma unroll
    for (int i = 0; i < 8; i += 2)
        split2(v[i] * inv, v[i + 1] * inv, hv[i >> 1], lv[i >> 1]);
    ((uint2*)(Ph + (size_t)row * SEQL + base))[0] = make_uint2(hv[0], hv[1]);
    ((uint2*)(Pl + (size_t)row * SEQL + base))[0] = make_uint2(lv[0], lv[1]);
    ((uint2*)(Ph + (size_t)row * SEQL + base))[1] = make_uint2(hv[2], hv[3]);
    ((uint2*)(Pl + (size_t)row * SEQL + base))[1] = make_uint2(lv[2], lv[3]);
}

// ---------------------------------------------------------------------------
#define SYM(p, s) do { void* _t; cudaGetSymbolAddress(&_t, s); p = (decltype(p))_t; } while (0)

extern "C" void kernel_launch(void* const* d_in, const int* in_sizes, int n_in,
                              void* d_out, int out_size)
{
    const float* values = (const float*)d_in[0];
    const float* keys   = (const float*)d_in[1];
    const float* query  = (const float*)d_in[2];
    const int*   mask   = (const int*)  d_in[3];
    const float* Wv     = (const float*)d_in[4];
    const float* Wk     = (const float*)d_in[5];
    const float* Wq     = (const float*)d_in[6];
    const float* Wo     = (const float*)d_in[7];
    const float* bo     = (const float*)d_in[8];
    float* out = (float*)d_out;

    __half *xvh, *xvl, *xkh, *xkl, *xqh, *xql;
    __half *wvh, *wvl, *wkh, *wkl, *wqh, *wql, *woh, *wol;
    __half *qh, *ql, *kh, *kl, *vth, *vtl, *ph, *pl, *oh, *ol;
    float* ge;
    SYM(xvh, g_xvh); SYM(xvl, g_xvl); SYM(xkh, g_xkh); SYM(xkl, g_xkl);
    SYM(xqh, g_xqh); SYM(xql, g_xql);
    SYM(wvh, g_wvh); SYM(wvl, g_wvl); SYM(wkh, g_wkh); SYM(wkl, g_wkl);
    SYM(wqh, g_wqh); SYM(wql, g_wql); SYM(woh, g_woh); SYM(wol, g_wol);
    SYM(qh, g_qh); SYM(ql, g_ql); SYM(kh, g_kh); SYM(kl, g_kl);
    SYM(vth, g_vth); SYM(vtl, g_vtl); SYM(ph, g_ph); SYM(pl, g_pl);
    SYM(oh, g_oh); SYM(ol, g_ol); SYM(ge, g_e);

    cudaFuncSetAttribute(hgemm<0>, cudaFuncAttributeMaxDynamicSharedMemorySize, GEMM_SMEM);
    cudaFuncSetAttribute(hgemm<1>, cudaFuncAttributeMaxDynamicSharedMemorySize, GEMM_SMEM);
    cudaFuncSetAttribute(hgemm<2>, cudaFuncAttributeMaxDynamicSharedMemorySize, GEMM_SMEM);
    cudaFuncSetAttribute(hgemm<3>, cudaFuncAttributeMaxDynamicSharedMemorySize, GEMM_SMEM);

    const int n4x = (int)(EX / 4), n4w = (int)(EW / 4);
    split_kernel<<<(n4x + 255) / 256, 256>>>(values, xvh, xvl, n4x);
    split_kernel<<<(n4x + 255) / 256, 256>>>(keys,   xkh, xkl, n4x);
    split_kernel<<<(n4x + 255) / 256, 256>>>(query,  xqh, xql, n4x);
    split_kernel<<<(n4w + 255) / 256, 256>>>(Wv, wvh, wvl, n4w);
    split_kernel<<<(n4w + 255) / 256, 256>>>(Wk, wkh, wkl, n4w);
    split_kernel<<<(n4w + 255) / 256, 256>>>(Wq, wqh, wql, n4w);
    split_kernel<<<(n4w + 255) / 256, 256>>>(Wo, woh, wol, n4w);

    // Q = Xq @ Wq^T, K = Xk @ Wk^T  (split fp16 out)
    hgemm<1><<<dim3(8, 64, 1), 256, GEMM_SMEM>>>(
        xqh, xql, wqh, wql, EMB, 0, 0, nullptr, nullptr, 0, EMB, qh, ql);
    hgemm<1><<<dim3(8, 64, 1), 256, GEMM_SMEM>>>(
        xkh, xkl, wkh, wkl, EMB, 0, 0, nullptr, nullptr, 0, EMB, kh, kl);
    // Vt = Wv @ Xv^T  (computed transposed; N-dim batch-folded output)
    hgemm<3><<<dim3(64, 8, 1), 256, GEMM_SMEM>>>(
        wvh, wvl, xvh, xvl, EMB, 0, 0, nullptr, nullptr, 0, SEQL, vth, vtl);

    // E = Q @ K^T per batch (fp32)
    hgemm<0><<<dim3(16, 16, NBAT), 256, GEMM_SMEM>>>(
        qh, ql, kh, kl, EMB, (size_t)SEQL * EMB, (size_t)SEQL * EMB,
        ge, nullptr, (size_t)SEQL * SEQL, SEQL, nullptr, nullptr);

    softmax_split<<<NBAT * SEQL, 256>>>(ge, mask, ph, pl);

    // O = P @ Vt^T per batch (split fp16 out)
    hgemm<1><<<dim3(8, 16, NBAT), 256, GEMM_SMEM>>>(
        ph, pl, vth, vtl, SEQL, (size_t)SEQL * SEQL, (size_t)EMB * SEQL,
        nullptr, nullptr, (size_t)SEQL * EMB, EMB, oh, ol);

    // out = O @ Wo^T + bo (fp32)
    hgemm<2><<<dim3(8, 64, 1), 256, GEMM_SMEM>>>(
        oh, ol, woh, wol, EMB, 0, 0, out, bo, 0, EMB, nullptr, nullptr);
}

// round 5
// speedup vs baseline: 2.8876x; 1.0310x over previous
#include <cuda_runtime.h>
#include <cuda_fp16.h>
#include <cstdint>
#include <cstddef>

// ---------------------------------------------------------------------------
#define NBAT 4
#define SEQL 2048
#define EMB  1024
#define MQ   (NBAT * SEQL)   /* 8192 */

static constexpr size_t EX = (size_t)MQ * EMB;
static constexpr size_t EW = (size_t)EMB * EMB;
static constexpr size_t EP = (size_t)NBAT * SEQL * SEQL;

// Scratch (__device__ statics)
__device__ __half g_xvh[EX], g_xvl[EX];
__device__ __half g_xkh[EX], g_xkl[EX];
__device__ __half g_xqh[EX], g_xql[EX];
__device__ __half g_wvh[EW], g_wvl[EW];
__device__ __half g_wkh[EW], g_wkl[EW];
__device__ __half g_wqh[EW], g_wql[EW];
__device__ __half g_woh[EW], g_wol[EW];
__device__ __half g_qh[EX],  g_ql[EX];
__device__ __half g_kh[EX],  g_kl[EX];
__device__ __half g_vth[EX], g_vtl[EX];   // V projected, stored [b][emb][seq]
__device__ float  g_e[EP];
__device__ __half g_ph[EP];               // softmax probs (hi only)
__device__ __half g_oh[EX],  g_ol[EX];

// ---------------------------------------------------------------------------
__device__ __forceinline__ uint32_t smem_u32(const void* p) {
    uint32_t a;
    asm("{ .reg .u64 t; cvta.to.shared.u64 t, %1; cvt.u32.u64 %0, t; }" : "=r"(a) : "l"(p));
    return a;
}
__device__ __forceinline__ void cp16(uint32_t s, const void* g) {
    asm volatile("cp.async.cg.shared.global [%0], [%1], 16;" :: "r"(s), "l"(g) : "memory");
}
#define CP_COMMIT() asm volatile("cp.async.commit_group;" ::: "memory")

__device__ __forceinline__ void ldsm4(uint32_t* r, uint32_t addr) {
    asm volatile("ldmatrix.sync.aligned.m8n8.x4.shared.b16 {%0,%1,%2,%3}, [%4];"
        : "=r"(r[0]), "=r"(r[1]), "=r"(r[2]), "=r"(r[3]) : "r"(addr));
}
__device__ __forceinline__ void mma16816(float* c, const uint32_t* a, const uint32_t* b) {
    asm volatile("mma.sync.aligned.m16n8k16.row.col.f32.f16.f16.f32 "
        "{%0,%1,%2,%3}, {%4,%5,%6,%7}, {%8,%9}, {%0,%1,%2,%3};"
        : "+f"(c[0]), "+f"(c[1]), "+f"(c[2]), "+f"(c[3])
        : "r"(a[0]), "r"(a[1]), "r"(a[2]), "r"(a[3]), "r"(b[0]), "r"(b[1]));
}

__device__ __forceinline__ void split2(float f0, float f1, uint32_t& hi, uint32_t& lo) {
    __half h0 = __float2half_rn(f0), h1 = __float2half_rn(f1);
    __half l0 = __float2half_rn(f0 - __half2float(h0));
    __half l1 = __float2half_rn(f1 - __half2float(h1));
    hi = (uint32_t)__half_as_ushort(h0) | ((uint32_t)__half_as_ushort(h1) << 16);
    lo = (uint32_t)__half_as_ushort(l0) | ((uint32_t)__half_as_ushort(l1) << 16);
}

// ---------------------------------------------------------------------------
// hi/lo-split HGEMM:
//   TERMS3: C = Ah*Bh^T + Ah*Bl^T + Al*Bh^T  (fp32 acc)
//  !TERMS3: C = Ah*Bh^T + Ah*Bl^T            (A lo side skipped entirely)
// A,B K-major [rows][K]. Tile 128x128x32, 256 thr, 3-stage cp.async.
// smem rows padded to 80B -> conflict-free ldmatrix.
// MODE: 0 fp32 | 1 split fp16 | 2 fp32+bias | 3 split fp16, N-dim batch-folded
// ---------------------------------------------------------------------------
#define STAGES 3
#define TILE_B 10240               /* 128 rows * 80 B */
#define STG_B  (4 * TILE_B)
#define GEMM_SMEM (STAGES * STG_B) /* 122880 */

template <int MODE, bool TERMS3>
__global__ __launch_bounds__(256)
void hgemm(const __half* __restrict__ Ah, const __half* __restrict__ Al,
           const __half* __restrict__ Bh, const __half* __restrict__ Bl,
           int K, size_t sA, size_t sB,
           float* __restrict__ Cf, const float* __restrict__ bias,
           size_t sC, int Nc,
           __half* __restrict__ Ch, __half* __restrict__ Cl)
{
    extern __shared__ char smc[];
    const uint32_t sb = smem_u32(smc);
    const int tid = threadIdx.x, lane = tid & 31, wid = tid >> 5;
    const int m0 = blockIdx.y * 128, n0 = blockIdx.x * 128, b = blockIdx.z;
    const int nch = K >> 5;

    const __half* srcs[4];
    srcs[0] = Ah + (size_t)b * sA + (size_t)m0 * K;
    srcs[1] = TERMS3 ? (Al + (size_t)b * sA + (size_t)m0 * K) : srcs[0];
    srcs[2] = Bh + (size_t)b * sB + (size_t)n0 * K;
    srcs[3] = Bl + (size_t)b * sB + (size_t)n0 * K;

    auto load_stage = [&](int s, int chunk) {
        const uint32_t dbase = sb + s * STG_B;
        const int k0 = chunk * 32;
        #pragma unroll
        for (int i = 0; i < 8; i++) {
            const int cid = tid + i * 256;
            const int tile = cid >> 9, r = (cid >> 2) & 127, seg = cid & 3;
            if (TERMS3 || tile != 1)
                cp16(dbase + tile * TILE_B + r * 80 + seg * 16,
                     srcs[tile] + (size_t)r * K + k0 + seg * 8);
        }
    };

    #pragma unroll
    for (int s = 0; s < STAGES - 1; s++) { load_stage(s, s); CP_COMMIT(); }

    const int m0w = (wid >> 2) * 64, n0w = (wid & 3) * 32;
    const uint32_t aoff = (uint32_t)(m0w + (lane & 15)) * 80 + ((lane >> 4) * 16);
    const uint32_t boff = (uint32_t)(n0w + ((lane >> 4) & 1) * 8 + (lane & 7)) * 80
                        + (((lane >> 3) & 1) * 16);

    float acc[4][4][4];
    #pragma unroll
    for (int a = 0; a < 4; a++)
        #pragma unroll
        for (int c = 0; c < 4; c++)
            #pragma unroll
            for (int d = 0; d < 4; d++) acc[a][c][d] = 0.f;

    for (int c = 0; c < nch; c++) {
        asm volatile("cp.async.wait_group %0;" :: "n"(STAGES - 2));
        __syncthreads();
        if (c + STAGES - 1 < nch) load_stage((c + STAGES - 1) % STAGES, c + STAGES - 1);
        CP_COMMIT();

        const uint32_t st = sb + (c % STAGES) * STG_B;
        const uint32_t aH = st + aoff, aL = st + TILE_B + aoff;
        const uint32_t bH = st + 2 * TILE_B + boff, bL = st + 3 * TILE_B + boff;

        #pragma unroll
        for (int ks = 0; ks < 2; ks++) {
            uint32_t ah[4][4], al[4][4], bh[4][2], bl[4][2];
            #pragma unroll
            for (int mi = 0; mi < 4; mi++) {
                ldsm4(ah[mi], aH + mi * 1280 + ks * 32);
                if (TERMS3) ldsm4(al[mi], aL + mi * 1280 + ks * 32);
            }
            #pragma unroll
            for (int j = 0; j < 2; j++) {
                uint32_t t[4];
                ldsm4(t, bH + j * 1280 + ks * 32);
                bh[2*j][0] = t[0]; bh[2*j][1] = t[1];
                bh[2*j+1][0] = t[2]; bh[2*j+1][1] = t[3];
                ldsm4(t, bL + j * 1280 + ks * 32);
                bl[2*j][0] = t[0]; bl[2*j][1] = t[1];
                bl[2*j+1][0] = t[2]; bl[2*j+1][1] = t[3];
            }
            #pragma unroll
            for (int mi = 0; mi < 4; mi++)
                #pragma unroll
                for (int ni = 0; ni < 4; ni++) {
                    mma16816(acc[mi][ni], ah[mi], bh[ni]);
                    mma16816(acc[mi][ni], ah[mi], bl[ni]);
                    if (TERMS3) mma16816(acc[mi][ni], al[mi], bh[ni]);
                }
        }
    }

    const int fr = lane >> 2, fc = (lane & 3) * 2;
    #pragma unroll
    for (int mi = 0; mi < 4; mi++)
        #pragma unroll
        for (int ni = 0; ni < 4; ni++) {
            const int row = m0 + m0w + mi * 16 + fr;
            const int col = n0 + n0w + ni * 8 + fc;
            float* pc = acc[mi][ni];
            if (MODE == 0 || MODE == 2) {
                float2 v0 = make_float2(pc[0], pc[1]);
                float2 v1 = make_float2(pc[2], pc[3]);
                if (MODE == 2) {
                    const float b0v = bias[col], b1v = bias[col + 1];
                    v0.x += b0v; v0.y += b1v; v1.x += b0v; v1.y += b1v;
                }
                float* base = Cf + (size_t)b * sC;
                *(float2*)(base + (size_t)row * Nc + col) = v0;
                *(float2*)(base + (size_t)(row + 8) * Nc + col) = v1;
            } else if (MODE == 1) {
                uint32_t h0, l0, h1, l1;
                split2(pc[0], pc[1], h0, l0);
                split2(pc[2], pc[3], h1, l1);
                const size_t i0 = (size_t)b * sC + (size_t)row * Nc + col;
                const size_t i1 = (size_t)b * sC + (size_t)(row + 8) * Nc + col;
                *(uint32_t*)(Ch + i0) = h0; *(uint32_t*)(Cl + i0) = l0;
                *(uint32_t*)(Ch + i1) = h1; *(uint32_t*)(Cl + i1) = l1;
            } else {
                uint32_t h0, l0, h1, l1;
                split2(pc[0], pc[1], h0, l0);
                split2(pc[2], pc[3], h1, l1);
                const size_t bb = (size_t)(col >> 11) * ((size_t)EMB * SEQL);
                const size_t i0 = bb + (size_t)row * SEQL + (col & 2047);
                const size_t i1 = i0 + (size_t)8 * SEQL;
                *(uint32_t*)(Ch + i0) = h0; *(uint32_t*)(Cl + i0) = l0;
                *(uint32_t*)(Ch + i1) = h1; *(uint32_t*)(Cl + i1) = l1;
            }
        }
}

// ---------------------------------------------------------------------------
// fp32 -> fp16 hi/lo split; up to 4 arrays in one launch (blockIdx.y selects)
// ---------------------------------------------------------------------------
struct SplitJob { const float* x; __half* h; __half* l; };

__global__ __launch_bounds__(256)
void split_multi(SplitJob j0, SplitJob j1, SplitJob j2, SplitJob j3, int n4)
{
    const SplitJob& j = (blockIdx.y == 0) ? j0 : (blockIdx.y == 1) ? j1
                      : (blockIdx.y == 2) ? j2 : j3;
    int i = blockIdx.x * 256 + threadIdx.x;
    if (i >= n4) return;
    float4 v = ((const float4*)j.x)[i];
    uint32_t h0, l0, h1, l1;
    split2(v.x, v.y, h0, l0);
    split2(v.z, v.w, h1, l1);
    ((uint2*)j.h)[i] = make_uint2(h0, h1);
    ((uint2*)j.l)[i] = make_uint2(l0, l1);
}

// ---------------------------------------------------------------------------
// masked softmax on fp32 E, writing fp16 (hi only) probabilities
// ---------------------------------------------------------------------------
__global__ __launch_bounds__(256)
void softmax_h(const float* __restrict__ E, const int* __restrict__ mask,
               __half* __restrict__ Ph)
{
    const int row = blockIdx.x;
    const int b = row >> 11;
    const float* e = E + (size_t)row * SEQL;
    const int* m = mask + (size_t)b * SEQL * SEQL + (size_t)(row & 2047) * SEQL;
    const int t = threadIdx.x;
    const int base = t * 8;

    float v[8];
    #pragma unroll
    for (int g = 0; g < 2; g++) {
        float4 ev = *(const float4*)(e + base + g * 4);
        int4 mv = *(const int4*)(m + base + g * 4);
        v[g*4+0] = ((mv.x == 0) ? -1e20f : ev.x) * 0.03125f;
        v[g*4+1] = ((mv.y == 0) ? -1e20f : ev.y) * 0.03125f;
        v[g*4+2] = ((mv.z == 0) ? -1e20f : ev.z) * 0.03125f;
        v[g*4+3] = ((mv.w == 0) ? -1e20f : ev.w) * 0.03125f;
    }
    float mx = -3.4e38f;
    #pragma unroll
    for (int i = 0; i < 8; i++) mx = fmaxf(mx, v[i]);

    __shared__ float red[256];
    red[t] = mx;
    __syncthreads();
    for (int s = 128; s > 0; s >>= 1) {
        if (t < s) red[t] = fmaxf(red[t], red[t + s]);
        __syncthreads();
    }
    mx = red[0];
    __syncthreads();

    float sum = 0.f;
    #pragma unroll
    for (int i = 0; i < 8; i++) { v[i] = __expf(v[i] - mx); sum += v[i]; }
    red[t] = sum;
    __syncthreads();
    for (int s = 128; s > 0; s >>= 1) {
        if (t < s) red[t] += red[t + s];
        __syncthreads();
    }
    const float inv = 1.f / red[0];

    uint2 hv;
    #pragma unroll
    for (int g = 0; g < 2; g++) {
        __half p0 = __float2half_rn(v[g*4+0] * inv);
        __half p1 = __float2half_rn(v[g*4+1] * inv);
        __half p2 = __float2half_rn(v[g*4+2] * inv);
        __half p3 = __float2half_rn(v[g*4+3] * inv);
        hv.x = (uint32_t)__half_as_ushort(p0) | ((uint32_t)__half_as_ushort(p1) << 16);
        hv.y = (uint32_t)__half_as_ushort(p2) | ((uint32_t)__half_as_ushort(p3) << 16);
        ((uint2*)(Ph + (size_t)row * SEQL + base))[g] = hv;
    }
}

// ---------------------------------------------------------------------------
#define SYM(p, s) do { void* _t; cudaGetSymbolAddress(&_t, s); p = (decltype(p))_t; } while (0)

extern "C" void kernel_launch(void* const* d_in, const int* in_sizes, int n_in,
                              void* d_out, int out_size)
{
    const float* values = (const float*)d_in[0];
    const float* keys   = (const float*)d_in[1];
    const float* query  = (const float*)d_in[2];
    const int*   mask   = (const int*)  d_in[3];
    const float* Wv     = (const float*)d_in[4];
    const float* Wk     = (const float*)d_in[5];
    const float* Wq     = (const float*)d_in[6];
    const float* Wo     = (const float*)d_in[7];
    const float* bo     = (const float*)d_in[8];
    float* out = (float*)d_out;

    __half *xvh, *xvl, *xkh, *xkl, *xqh, *xql;
    __half *wvh, *wvl, *wkh, *wkl, *wqh, *wql, *woh, *wol;
    __half *qh, *ql, *kh, *kl, *vth, *vtl, *ph, *oh, *ol;
    float* ge;
    SYM(xvh, g_xvh); SYM(xvl, g_xvl); SYM(xkh, g_xkh); SYM(xkl, g_xkl);
    SYM(xqh, g_xqh); SYM(xql, g_xql);
    SYM(wvh, g_wvh); SYM(wvl, g_wvl); SYM(wkh, g_wkh); SYM(wkl, g_wkl);
    SYM(wqh, g_wqh); SYM(wql, g_wql); SYM(woh, g_woh); SYM(wol, g_wol);
    SYM(qh, g_qh); SYM(ql, g_ql); SYM(kh, g_kh); SYM(kl, g_kl);
    SYM(vth, g_vth); SYM(vtl, g_vtl); SYM(ph, g_ph);
    SYM(oh, g_oh); SYM(ol, g_ol); SYM(ge, g_e);

    cudaFuncSetAttribute(hgemm<0, true>,  cudaFuncAttributeMaxDynamicSharedMemorySize, GEMM_SMEM);
    cudaFuncSetAttribute(hgemm<1, true>,  cudaFuncAttributeMaxDynamicSharedMemorySize, GEMM_SMEM);
    cudaFuncSetAttribute(hgemm<1, false>, cudaFuncAttributeMaxDynamicSharedMemorySize, GEMM_SMEM);
    cudaFuncSetAttribute(hgemm<2, true>,  cudaFuncAttributeMaxDynamicSharedMemorySize, GEMM_SMEM);
    cudaFuncSetAttribute(hgemm<3, true>,  cudaFuncAttributeMaxDynamicSharedMemorySize, GEMM_SMEM);

    const int n4x = (int)(EX / 4), n4w = (int)(EW / 4);
    // inputs: 3 arrays in one launch (4th slot duplicates #0 harmlessly? no —
    // use gridDim.y = 3 exactly)
    {
        SplitJob jv{values, xvh, xvl}, jk{keys, xkh, xkl}, jq{query, xqh, xql};
        split_multi<<<dim3((n4x + 255) / 256, 3, 1), 256>>>(jv, jk, jq, jq, n4x);
        SplitJob wv{Wv, wvh, wvl}, wk{Wk, wkh, wkl}, wq{Wq, wqh, wql}, wo{Wo, woh, wol};
        split_multi<<<dim3((n4w + 255) / 256, 4, 1), 256>>>(wv, wk, wq, wo, n4w);
    }

    // Q = Xq @ Wq^T, K = Xk @ Wk^T  (split fp16 out)
    hgemm<1, true><<<dim3(8, 64, 1), 256, GEMM_SMEM>>>(
        xqh, xql, wqh, wql, EMB, 0, 0, nullptr, nullptr, 0, EMB, qh, ql);
    hgemm<1, true><<<dim3(8, 64, 1), 256, GEMM_SMEM>>>(
        xkh, xkl, wkh, wkl, EMB, 0, 0, nullptr, nullptr, 0, EMB, kh, kl);
    // Vt = Wv @ Xv^T  (computed transposed; N-dim batch-folded output)
    hgemm<3, true><<<dim3(64, 8, 1), 256, GEMM_SMEM>>>(
        wvh, wvl, xvh, xvl, EMB, 0, 0, nullptr, nullptr, 0, SEQL, vth, vtl);

    // E = Q @ K^T per batch (fp32)
    hgemm<0, true><<<dim3(16, 16, NBAT), 256, GEMM_SMEM>>>(
        qh, ql, kh, kl, EMB, (size_t)SEQL * EMB, (size_t)SEQL * EMB,
        ge, nullptr, (size_t)SEQL * SEQL, SEQL, nullptr, nullptr);

    softmax_h<<<NBAT * SEQL, 256>>>(ge, mask, ph);

    // O = Ph @ Vt^T per batch, 2 terms (P has no lo side)
    hgemm<1, false><<<dim3(8, 16, NBAT), 256, GEMM_SMEM>>>(
        ph, ph, vth, vtl, SEQL, (size_t)SEQL * SEQL, (size_t)EMB * SEQL,
        nullptr, nullptr, (size_t)SEQL * EMB, EMB, oh, ol);

    // out = O @ Wo^T + bo (fp32)
    hgemm<2, true><<<dim3(8, 64, 1), 256, GEMM_SMEM>>>(
        oh, ol, woh, wol, EMB, 0, 0, out, bo, 0, EMB, nullptr, nullptr);
}

// round 7
// speedup vs baseline: 3.2371x; 1.1210x over previous
#include <cuda_runtime.h>
#include <cuda_fp16.h>
#include <cstdint>
#include <cstddef>

// ---------------------------------------------------------------------------
#define NBAT 4
#define SEQL 2048
#define EMB  1024
#define MQ   (NBAT * SEQL)   /* 8192 */

static constexpr size_t EX = (size_t)MQ * EMB;
static constexpr size_t EW = (size_t)EMB * EMB;
static constexpr size_t EP = (size_t)NBAT * SEQL * SEQL;

// Scratch (__device__ statics)
__device__ __half g_xvh[EX], g_xvl[EX];
__device__ __half g_xkh[EX], g_xkl[EX];
__device__ __half g_xqh[EX], g_xql[EX];
__device__ __half g_wvh[EW], g_wvl[EW];
__device__ __half g_wkh[EW], g_wkl[EW];
__device__ __half g_wqh[EW], g_wql[EW];
__device__ __half g_woh[EW], g_wol[EW];
__device__ __half g_qh[EX],  g_ql[EX];
__device__ __half g_kh[EX],  g_kl[EX];
__device__ __half g_vth[EX], g_vtl[EX];   // V projected, stored [b][emb][seq]
__device__ float  g_e[EP];
__device__ __half g_ph[EP];               // softmax probs (hi only)
__device__ __half g_oh[EX],  g_ol[EX];

// ---------------------------------------------------------------------------
__device__ __forceinline__ uint32_t smem_u32(const void* p) {
    uint32_t a;
    asm("{ .reg .u64 t; cvta.to.shared.u64 t, %1; cvt.u32.u64 %0, t; }" : "=r"(a) : "l"(p));
    return a;
}
__device__ __forceinline__ void cp16(uint32_t s, const void* g) {
    asm volatile("cp.async.cg.shared.global [%0], [%1], 16;" :: "r"(s), "l"(g) : "memory");
}
#define CP_COMMIT() asm volatile("cp.async.commit_group;" ::: "memory")

__device__ __forceinline__ void ldsm4(uint32_t* r, uint32_t addr) {
    asm volatile("ldmatrix.sync.aligned.m8n8.x4.shared.b16 {%0,%1,%2,%3}, [%4];"
        : "=r"(r[0]), "=r"(r[1]), "=r"(r[2]), "=r"(r[3]) : "r"(addr));
}
__device__ __forceinline__ void mma16816(float* c, const uint32_t* a, const uint32_t* b) {
    asm volatile("mma.sync.aligned.m16n8k16.row.col.f32.f16.f16.f32 "
        "{%0,%1,%2,%3}, {%4,%5,%6,%7}, {%8,%9}, {%0,%1,%2,%3};"
        : "+f"(c[0]), "+f"(c[1]), "+f"(c[2]), "+f"(c[3])
        : "r"(a[0]), "r"(a[1]), "r"(a[2]), "r"(a[3]), "r"(b[0]), "r"(b[1]));
}

__device__ __forceinline__ void split2(float f0, float f1, uint32_t& hi, uint32_t& lo) {
    __half h0 = __float2half_rn(f0), h1 = __float2half_rn(f1);
    __half l0 = __float2half_rn(f0 - __half2float(h0));
    __half l1 = __float2half_rn(f1 - __half2float(h1));
    hi = (uint32_t)__half_as_ushort(h0) | ((uint32_t)__half_as_ushort(h1) << 16);
    lo = (uint32_t)__half_as_ushort(l0) | ((uint32_t)__half_as_ushort(l1) << 16);
}

// ---------------------------------------------------------------------------
// hi/lo-split HGEMM:
//   TERMS3: C = Ah*Bh^T + Ah*Bl^T + Al*Bh^T  (fp32 acc)
//  !TERMS3: C = Ah*Bh^T + Ah*Bl^T            (A lo side skipped entirely)
// A,B K-major [rows][K]. Tile 128x128x32, 256 thr, 2-stage cp.async,
// 2 CTAs/SM (smem 80KB, regs capped 128).
// smem rows padded to 80B -> conflict-free ldmatrix.
// MODE: 0 fp32 | 1 split fp16 | 2 fp32+bias | 3 split fp16, N-dim batch-folded
// ---------------------------------------------------------------------------
#define STAGES 2
#define TILE_B 10240               /* 128 rows * 80 B */
#define STG_B  (4 * TILE_B)
#define GEMM_SMEM (STAGES * STG_B) /* 81920 */

template <int MODE, bool TERMS3>
__global__ __launch_bounds__(256, 2)
void hgemm(const __half* __restrict__ Ah, const __half* __restrict__ Al,
           const __half* __restrict__ Bh, const __half* __restrict__ Bl,
           int K, size_t sA, size_t sB,
           float* __restrict__ Cf, const float* __restrict__ bias,
           size_t sC, int Nc,
           __half* __restrict__ Ch, __half* __restrict__ Cl)
{
    extern __shared__ char smc[];
    const uint32_t sb = smem_u32(smc);
    const int tid = threadIdx.x, lane = tid & 31, wid = tid >> 5;
    const int m0 = blockIdx.y * 128, n0 = blockIdx.x * 128, b = blockIdx.z;
    const int nch = K >> 5;

    const __half* srcs[4];
    srcs[0] = Ah + (size_t)b * sA + (size_t)m0 * K;
    srcs[1] = TERMS3 ? (Al + (size_t)b * sA + (size_t)m0 * K) : srcs[0];
    srcs[2] = Bh + (size_t)b * sB + (size_t)n0 * K;
    srcs[3] = Bl + (size_t)b * sB + (size_t)n0 * K;

    auto load_stage = [&](int s, int chunk) {
        const uint32_t dbase = sb + s * STG_B;
        const int k0 = chunk * 32;
        #pragma unroll
        for (int i = 0; i < 8; i++) {
            const int cid = tid + i * 256;
            const int tile = cid >> 9, r = (cid >> 2) & 127, seg = cid & 3;
            if (TERMS3 || tile != 1)
                cp16(dbase + tile * TILE_B + r * 80 + seg * 16,
                     srcs[tile] + (size_t)r * K + k0 + seg * 8);
        }
    };

    load_stage(0, 0);
    CP_COMMIT();

    const int m0w = (wid >> 2) * 64, n0w = (wid & 3) * 32;
    const uint32_t aoff = (uint32_t)(m0w + (lane & 15)) * 80 + ((lane >> 4) * 16);
    const uint32_t boff = (uint32_t)(n0w + ((lane >> 4) & 1) * 8 + (lane & 7)) * 80
                        + (((lane >> 3) & 1) * 16);

    float acc[4][4][4];
    #pragma unroll
    for (int a = 0; a < 4; a++)
        #pragma unroll
        for (int c = 0; c < 4; c++)
            #pragma unroll
            for (int d = 0; d < 4; d++) acc[a][c][d] = 0.f;

    for (int c = 0; c < nch; c++) {
        asm volatile("cp.async.wait_group 0;" ::: "memory");
        __syncthreads();
        if (c + 1 < nch) load_stage((c + 1) & 1, c + 1);
        CP_COMMIT();

        const uint32_t st = sb + (c & 1) * STG_B;
        const uint32_t aH = st + aoff, aL = st + TILE_B + aoff;
        const uint32_t bH = st + 2 * TILE_B + boff, bL = st + 3 * TILE_B + boff;

        #pragma unroll
        for (int ks = 0; ks < 2; ks++) {
            uint32_t ah[4][4], al[4][4], bh[4][2], bl[4][2];
            #pragma unroll
            for (int mi = 0; mi < 4; mi++) {
                ldsm4(ah[mi], aH + mi * 1280 + ks * 32);
                if (TERMS3) ldsm4(al[mi], aL + mi * 1280 + ks * 32);
            }
            #pragma unroll
            for (int j = 0; j < 2; j++) {
                uint32_t t[4];
                ldsm4(t, bH + j * 1280 + ks * 32);
                bh[2*j][0] = t[0]; bh[2*j][1] = t[1];
                bh[2*j+1][0] = t[2]; bh[2*j+1][1] = t[3];
                ldsm4(t, bL + j * 1280 + ks * 32);
                bl[2*j][0] = t[0]; bl[2*j][1] = t[1];
                bl[2*j+1][0] = t[2]; bl[2*j+1][1] = t[3];
            }
            #pragma unroll
            for (int mi = 0; mi < 4; mi++)
                #pragma unroll
                for (int ni = 0; ni < 4; ni++) {
                    mma16816(acc[mi][ni], ah[mi], bh[ni]);
                    mma16816(acc[mi][ni], ah[mi], bl[ni]);
                    if (TERMS3) mma16816(acc[mi][ni], al[mi], bh[ni]);
                }
        }
    }

    const int fr = lane >> 2, fc = (lane & 3) * 2;
    #pragma unroll
    for (int mi = 0; mi < 4; mi++)
        #pragma unroll
        for (int ni = 0; ni < 4; ni++) {
            const int row = m0 + m0w + mi * 16 + fr;
            const int col = n0 + n0w + ni * 8 + fc;
            float* pc = acc[mi][ni];
            if (MODE == 0 || MODE == 2) {
                float2 v0 = make_float2(pc[0], pc[1]);
                float2 v1 = make_float2(pc[2], pc[3]);
                if (MODE == 2) {
                    const float b0v = bias[col], b1v = bias[col + 1];
                    v0.x += b0v; v0.y += b1v; v1.x += b0v; v1.y += b1v;
                }
                float* base = Cf + (size_t)b * sC;
                *(float2*)(base + (size_t)row * Nc + col) = v0;
                *(float2*)(base + (size_t)(row + 8) * Nc + col) = v1;
            } else if (MODE == 1) {
                uint32_t h0, l0, h1, l1;
                split2(pc[0], pc[1], h0, l0);
                split2(pc[2], pc[3], h1, l1);
                const size_t i0 = (size_t)b * sC + (size_t)row * Nc + col;
                const size_t i1 = (size_t)b * sC + (size_t)(row + 8) * Nc + col;
                *(uint32_t*)(Ch + i0) = h0; *(uint32_t*)(Cl + i0) = l0;
                *(uint32_t*)(Ch + i1) = h1; *(uint32_t*)(Cl + i1) = l1;
            } else {
                uint32_t h0, l0, h1, l1;
                split2(pc[0], pc[1], h0, l0);
                split2(pc[2], pc[3], h1, l1);
                const size_t bb = (size_t)(col >> 11) * ((size_t)EMB * SEQL);
                const size_t i0 = bb + (size_t)row * SEQL + (col & 2047);
                const size_t i1 = i0 + (size_t)8 * SEQL;
                *(uint32_t*)(Ch + i0) = h0; *(uint32_t*)(Cl + i0) = l0;
                *(uint32_t*)(Ch + i1) = h1; *(uint32_t*)(Cl + i1) = l1;
            }
        }
}

// ---------------------------------------------------------------------------
// fp32 -> fp16 hi/lo split; up to 4 arrays in one launch (blockIdx.y selects)
// ---------------------------------------------------------------------------
struct SplitJob { const float* x; __half* h; __half* l; };

__global__ __launch_bounds__(256)
void split_multi(SplitJob j0, SplitJob j1, SplitJob j2, SplitJob j3, int n4)
{
    const SplitJob& j = (blockIdx.y == 0) ? j0 : (blockIdx.y == 1) ? j1
                      : (blockIdx.y == 2) ? j2 : j3;
    int i = blockIdx.x * 256 + threadIdx.x;
    if (i >= n4) return;
    float4 v = ((const float4*)j.x)[i];
    uint32_t h0, l0, h1, l1;
    split2(v.x, v.y, h0, l0);
    split2(v.z, v.w, h1, l1);
    ((uint2*)j.h)[i] = make_uint2(h0, h1);
    ((uint2*)j.l)[i] = make_uint2(l0, l1);
}

// ---------------------------------------------------------------------------
// masked softmax on fp32 E, writing fp16 (hi only) probabilities
// ---------------------------------------------------------------------------
__global__ __launch_bounds__(256)
void softmax_h(const float* __restrict__ E, const int* __restrict__ mask,
               __half* __restrict__ Ph)
{
    const int row = blockIdx.x;
    const int b = row >> 11;
    const float* e = E + (size_t)row * SEQL;
    const int* m = mask + (size_t)b * SEQL * SEQL + (size_t)(row & 2047) * SEQL;
    const int t = threadIdx.x;
    const int base = t * 8;

    float v[8];
    #pragma unroll
    for (int g = 0; g < 2; g++) {
        float4 ev = *(const float4*)(e + base + g * 4);
        int4 mv = *(const int4*)(m + base + g * 4);
        v[g*4+0] = ((mv.x == 0) ? -1e20f : ev.x) * 0.03125f;
        v[g*4+1] = ((mv.y == 0) ? -1e20f : ev.y) * 0.03125f;
        v[g*4+2] = ((mv.z == 0) ? -1e20f : ev.z) * 0.03125f;
        v[g*4+3] = ((mv.w == 0) ? -1e20f : ev.w) * 0.03125f;
    }
    float mx = -3.4e38f;
    #pragma unroll
    for (int i = 0; i < 8; i++) mx = fmaxf(mx, v[i]);

    __shared__ float red[256];
    red[t] = mx;
    __syncthreads();
    for (int s = 128; s > 0; s >>= 1) {
        if (t < s) red[t] = fmaxf(red[t], red[t + s]);
        __syncthreads();
    }
    mx = red[0];
    __syncthreads();

    float sum = 0.f;
    #pragma unroll
    for (int i = 0; i < 8; i++) { v[i] = __expf(v[i] - mx); sum += v[i]; }
    red[t] = sum;
    __syncthreads();
    for (int s = 128; s > 0; s >>= 1) {
        if (t < s) red[t] += red[t + s];
        __syncthreads();
    }
    const float inv = 1.f / red[0];

    uint2 hv;
    #pragma unroll
    for (int g = 0; g < 2; g++) {
        __half p0 = __float2half_rn(v[g*4+0] * inv);
        __half p1 = __float2half_rn(v[g*4+1] * inv);
        __half p2 = __float2half_rn(v[g*4+2] * inv);
        __half p3 = __float2half_rn(v[g*4+3] * inv);
        hv.x = (uint32_t)__half_as_ushort(p0) | ((uint32_t)__half_as_ushort(p1) << 16);
        hv.y = (uint32_t)__half_as_ushort(p2) | ((uint32_t)__half_as_ushort(p3) << 16);
        ((uint2*)(Ph + (size_t)row * SEQL + base))[g] = hv;
    }
}

// ---------------------------------------------------------------------------
#define SYM(p, s) do { void* _t; cudaGetSymbolAddress(&_t, s); p = (decltype(p))_t; } while (0)

extern "C" void kernel_launch(void* const* d_in, const int* in_sizes, int n_in,
                              void* d_out, int out_size)
{
    const float* values = (const float*)d_in[0];
    const float* keys   = (const float*)d_in[1];
    const float* query  = (const float*)d_in[2];
    const int*   mask   = (const int*)  d_in[3];
    const float* Wv     = (const float*)d_in[4];
    const float* Wk     = (const float*)d_in[5];
    const float* Wq     = (const float*)d_in[6];
    const float* Wo     = (const float*)d_in[7];
    const float* bo     = (const float*)d_in[8];
    float* out = (float*)d_out;

    __half *xvh, *xvl, *xkh, *xkl, *xqh, *xql;
    __half *wvh, *wvl, *wkh, *wkl, *wqh, *wql, *woh, *wol;
    __half *qh, *ql, *kh, *kl, *vth, *vtl, *ph, *oh, *ol;
    float* ge;
    SYM(xvh, g_xvh); SYM(xvl, g_xvl); SYM(xkh, g_xkh); SYM(xkl, g_xkl);
    SYM(xqh, g_xqh); SYM(xql, g_xql);
    SYM(wvh, g_wvh); SYM(wvl, g_wvl); SYM(wkh, g_wkh); SYM(wkl, g_wkl);
    SYM(wqh, g_wqh); SYM(wql, g_wql); SYM(woh, g_woh); SYM(wol, g_wol);
    SYM(qh, g_qh); SYM(ql, g_ql); SYM(kh, g_kh); SYM(kl, g_kl);
    SYM(vth, g_vth); SYM(vtl, g_vtl); SYM(ph, g_ph);
    SYM(oh, g_oh); SYM(ol, g_ol); SYM(ge, g_e);

    cudaFuncSetAttribute(hgemm<0, true>,  cudaFuncAttributeMaxDynamicSharedMemorySize, GEMM_SMEM);
    cudaFuncSetAttribute(hgemm<1, true>,  cudaFuncAttributeMaxDynamicSharedMemorySize, GEMM_SMEM);
    cudaFuncSetAttribute(hgemm<1, false>, cudaFuncAttributeMaxDynamicSharedMemorySize, GEMM_SMEM);
    cudaFuncSetAttribute(hgemm<2, true>,  cudaFuncAttributeMaxDynamicSharedMemorySize, GEMM_SMEM);
    cudaFuncSetAttribute(hgemm<3, true>,  cudaFuncAttributeMaxDynamicSharedMemorySize, GEMM_SMEM);

    const int n4x = (int)(EX / 4), n4w = (int)(EW / 4);
    {
        SplitJob jv{values, xvh, xvl}, jk{keys, xkh, xkl}, jq{query, xqh, xql};
        split_multi<<<dim3((n4x + 255) / 256, 3, 1), 256>>>(jv, jk, jq, jq, n4x);
        SplitJob wv{Wv, wvh, wvl}, wk{Wk, wkh, wkl}, wq{Wq, wqh, wql}, wo{Wo, woh, wol};
        split_multi<<<dim3((n4w + 255) / 256, 4, 1), 256>>>(wv, wk, wq, wo, n4w);
    }

    // Q = Xq @ Wq^T, K = Xk @ Wk^T  (split fp16 out)
    hgemm<1, true><<<dim3(8, 64, 1), 256, GEMM_SMEM>>>(
        xqh, xql, wqh, wql, EMB, 0, 0, nullptr, nullptr, 0, EMB, qh, ql);
    hgemm<1, true><<<dim3(8, 64, 1), 256, GEMM_SMEM>>>(
        xkh, xkl, wkh, wkl, EMB, 0, 0, nullptr, nullptr, 0, EMB, kh, kl);
    // Vt = Wv @ Xv^T  (computed transposed; N-dim batch-folded output)
    hgemm<3, true><<<dim3(64, 8, 1), 256, GEMM_SMEM>>>(
        wvh, wvl, xvh, xvl, EMB, 0, 0, nullptr, nullptr, 0, SEQL, vth, vtl);

    // E = Q @ K^T per batch (fp32)
    hgemm<0, true><<<dim3(16, 16, NBAT), 256, GEMM_SMEM>>>(
        qh, ql, kh, kl, EMB, (size_t)SEQL * EMB, (size_t)SEQL * EMB,
        ge, nullptr, (size_t)SEQL * SEQL, SEQL, nullptr, nullptr);

    softmax_h<<<NBAT * SEQL, 256>>>(ge, mask, ph);

    // O = Ph @ Vt^T per batch, 2 terms (P has no lo side)
    hgemm<1, false><<<dim3(8, 16, NBAT), 256, GEMM_SMEM>>>(
        ph, ph, vth, vtl, SEQL, (size_t)SEQL * SEQL, (size_t)EMB * SEQL,
        nullptr, nullptr, (size_t)SEQL * EMB, EMB, oh, ol);

    // out = O @ Wo^T + bo (fp32)
    hgemm<2, true><<<dim3(8, 64, 1), 256, GEMM_SMEM>>>(
        oh, ol, woh, wol, EMB, 0, 0, out, bo, 0, EMB, nullptr, nullptr);
}

// round 8
// speedup vs baseline: 4.3544x; 1.3452x over previous
#include <cuda_runtime.h>
#include <cuda_fp16.h>
#include <cstdint>
#include <cstddef>

// ---------------------------------------------------------------------------
#define NBAT 4
#define SEQL 2048
#define EMB  1024
#define MQ   (NBAT * SEQL)   /* 8192 */

static constexpr size_t EX = (size_t)MQ * EMB;
static constexpr size_t EW = (size_t)EMB * EMB;
static constexpr size_t EP = (size_t)NBAT * SEQL * SEQL;

// Scratch (__device__ statics)
__device__ __half g_xvh[EX], g_xvl[EX];   // values split (B of V-proj)
__device__ __half g_xkh[EX];              // keys hi (A of K-proj)
__device__ __half g_xqh[EX];              // query hi (A of Q-proj)
__device__ __half g_wvh[EW], g_wvl[EW];
__device__ __half g_wkh[EW], g_wkl[EW];
__device__ __half g_wqh[EW], g_wql[EW];
__device__ __half g_woh[EW], g_wol[EW];
__device__ __half g_qh[EX];               // projected Q (hi only)
__device__ __half g_kh[EX],  g_kl[EX];    // projected K split
__device__ __half g_vth[EX], g_vtl[EX];   // projected V split, [b][emb][seq]
__device__ float  g_e[EP];
__device__ __half g_ph[EP];               // softmax probs (hi only)
__device__ __half g_oh[EX];               // attn @ V (hi only)

// ---------------------------------------------------------------------------
__device__ __forceinline__ uint32_t smem_u32(const void* p) {
    uint32_t a;
    asm("{ .reg .u64 t; cvta.to.shared.u64 t, %1; cvt.u32.u64 %0, t; }" : "=r"(a) : "l"(p));
    return a;
}
__device__ __forceinline__ void cp16(uint32_t s, const void* g) {
    asm volatile("cp.async.cg.shared.global [%0], [%1], 16;" :: "r"(s), "l"(g) : "memory");
}
#define CP_COMMIT() asm volatile("cp.async.commit_group;" ::: "memory")

__device__ __forceinline__ void ldsm4(uint32_t* r, uint32_t addr) {
    asm volatile("ldmatrix.sync.aligned.m8n8.x4.shared.b16 {%0,%1,%2,%3}, [%4];"
        : "=r"(r[0]), "=r"(r[1]), "=r"(r[2]), "=r"(r[3]) : "r"(addr));
}
__device__ __forceinline__ void mma16816(float* c, const uint32_t* a, const uint32_t* b) {
    asm volatile("mma.sync.aligned.m16n8k16.row.col.f32.f16.f16.f32 "
        "{%0,%1,%2,%3}, {%4,%5,%6,%7}, {%8,%9}, {%0,%1,%2,%3};"
        : "+f"(c[0]), "+f"(c[1]), "+f"(c[2]), "+f"(c[3])
        : "r"(a[0]), "r"(a[1]), "r"(a[2]), "r"(a[3]), "r"(b[0]), "r"(b[1]));
}

__device__ __forceinline__ void split2(float f0, float f1, uint32_t& hi, uint32_t& lo) {
    __half h0 = __float2half_rn(f0), h1 = __float2half_rn(f1);
    __half l0 = __float2half_rn(f0 - __half2float(h0));
    __half l1 = __float2half_rn(f1 - __half2float(h1));
    hi = (uint32_t)__half_as_ushort(h0) | ((uint32_t)__half_as_ushort(h1) << 16);
    lo = (uint32_t)__half_as_ushort(l0) | ((uint32_t)__half_as_ushort(l1) << 16);
}
__device__ __forceinline__ uint32_t pack2(float f0, float f1) {
    return (uint32_t)__half_as_ushort(__float2half_rn(f0))
         | ((uint32_t)__half_as_ushort(__float2half_rn(f1)) << 16);
}

// ---------------------------------------------------------------------------
// 2-term split HGEMM:  C = Ah*Bh^T + Ah*Bl^T   (fp32 accumulate)
// A,B K-major [rows][K]. Tile 128x128x32, 256 thr, 2-stage cp.async,
// 2 CTAs/SM (smem 60KB, regs capped 128). smem rows padded to 80B.
// MMA issued term-major: 16 independent HMMA per term -> no acc RAW chains.
// MODE: 0 fp32 | 1 split fp16 | 2 fp32+bias | 3 split fp16 batch-folded (V)
//       4 fp16 hi-only
// ---------------------------------------------------------------------------
#define TILE_B 10240               /* 128 rows * 80 B */
#define STG_B  (3 * TILE_B)        /* Ah, Bh, Bl */
#define GEMM_SMEM (2 * STG_B)      /* 61440 */

template <int MODE>
__global__ __launch_bounds__(256, 2)
void hgemm(const __half* __restrict__ Ah,
           const __half* __restrict__ Bh, const __half* __restrict__ Bl,
           int K, size_t sA, size_t sB,
           float* __restrict__ Cf, const float* __restrict__ bias,
           size_t sC, int Nc,
           __half* __restrict__ Ch, __half* __restrict__ Cl)
{
    extern __shared__ char smc[];
    const uint32_t sb = smem_u32(smc);
    const int tid = threadIdx.x, lane = tid & 31, wid = tid >> 5;
    const int m0 = blockIdx.y * 128, n0 = blockIdx.x * 128, b = blockIdx.z;
    const int nch = K >> 5;

    const __half* srcs[3];
    srcs[0] = Ah + (size_t)b * sA + (size_t)m0 * K;
    srcs[1] = Bh + (size_t)b * sB + (size_t)n0 * K;
    srcs[2] = Bl + (size_t)b * sB + (size_t)n0 * K;

    // producer: 1536 cp16 per stage / 256 thr = 6 each
    auto load_stage = [&](int s, int chunk) {
        const uint32_t dbase = sb + s * STG_B;
        const int k0 = chunk * 32;
        #pragma unroll
        for (int i = 0; i < 6; i++) {
            const int cid = tid + i * 256;
            const int tile = cid >> 9, r = (cid >> 2) & 127, seg = cid & 3;
            cp16(dbase + tile * TILE_B + r * 80 + seg * 16,
                 srcs[tile] + (size_t)r * K + k0 + seg * 8);
        }
    };

    load_stage(0, 0);
    CP_COMMIT();

    const int m0w = (wid >> 2) * 64, n0w = (wid & 3) * 32;
    const uint32_t aoff = (uint32_t)(m0w + (lane & 15)) * 80 + ((lane >> 4) * 16);
    const uint32_t boff = (uint32_t)(n0w + ((lane >> 4) & 1) * 8 + (lane & 7)) * 80
                        + (((lane >> 3) & 1) * 16);

    float acc[4][4][4];
    #pragma unroll
    for (int a = 0; a < 4; a++)
        #pragma unroll
        for (int c = 0; c < 4; c++)
            #pragma unroll
            for (int d = 0; d < 4; d++) acc[a][c][d] = 0.f;

    for (int c = 0; c < nch; c++) {
        asm volatile("cp.async.wait_group 0;" ::: "memory");
        __syncthreads();
        if (c + 1 < nch) load_stage((c + 1) & 1, c + 1);
        CP_COMMIT();

        const uint32_t st = sb + (c & 1) * STG_B;
        const uint32_t aH = st + aoff;
        const uint32_t bH = st + TILE_B + boff, bL = st + 2 * TILE_B + boff;

        #pragma unroll
        for (int ks = 0; ks < 2; ks++) {
            uint32_t ah[4][4], bh[4][2], bl[4][2];
            #pragma unroll
            for (int mi = 0; mi < 4; mi++)
                ldsm4(ah[mi], aH + mi * 1280 + ks * 32);
            #pragma unroll
            for (int j = 0; j < 2; j++) {
                uint32_t t[4];
                ldsm4(t, bH + j * 1280 + ks * 32);
                bh[2*j][0] = t[0]; bh[2*j][1] = t[1];
                bh[2*j+1][0] = t[2]; bh[2*j+1][1] = t[3];
                ldsm4(t, bL + j * 1280 + ks * 32);
                bl[2*j][0] = t[0]; bl[2*j][1] = t[1];
                bl[2*j+1][0] = t[2]; bl[2*j+1][1] = t[3];
            }
            // term-major: 16 independent MMAs, then 16 more
            #pragma unroll
            for (int mi = 0; mi < 4; mi++)
                #pragma unroll
                for (int ni = 0; ni < 4; ni++)
                    mma16816(acc[mi][ni], ah[mi], bh[ni]);
            #pragma unroll
            for (int mi = 0; mi < 4; mi++)
                #pragma unroll
                for (int ni = 0; ni < 4; ni++)
                    mma16816(acc[mi][ni], ah[mi], bl[ni]);
        }
    }

    const int fr = lane >> 2, fc = (lane & 3) * 2;
    #pragma unroll
    for (int mi = 0; mi < 4; mi++)
        #pragma unroll
        for (int ni = 0; ni < 4; ni++) {
            const int row = m0 + m0w + mi * 16 + fr;
            const int col = n0 + n0w + ni * 8 + fc;
            float* pc = acc[mi][ni];
            if (MODE == 0 || MODE == 2) {
                float2 v0 = make_float2(pc[0], pc[1]);
                float2 v1 = make_float2(pc[2], pc[3]);
                if (MODE == 2) {
                    const float b0v = bias[col], b1v = bias[col + 1];
                    v0.x += b0v; v0.y += b1v; v1.x += b0v; v1.y += b1v;
                }
                float* base = Cf + (size_t)b * sC;
                *(float2*)(base + (size_t)row * Nc + col) = v0;
                *(float2*)(base + (size_t)(row + 8) * Nc + col) = v1;
            } else if (MODE == 1) {
                uint32_t h0, l0, h1, l1;
                split2(pc[0], pc[1], h0, l0);
                split2(pc[2], pc[3], h1, l1);
                const size_t i0 = (size_t)b * sC + (size_t)row * Nc + col;
                const size_t i1 = (size_t)b * sC + (size_t)(row + 8) * Nc + col;
                *(uint32_t*)(Ch + i0) = h0; *(uint32_t*)(Cl + i0) = l0;
                *(uint32_t*)(Ch + i1) = h1; *(uint32_t*)(Cl + i1) = l1;
            } else if (MODE == 3) {
                uint32_t h0, l0, h1, l1;
                split2(pc[0], pc[1], h0, l0);
                split2(pc[2], pc[3], h1, l1);
                const size_t bb = (size_t)(col >> 11) * ((size_t)EMB * SEQL);
                const size_t i0 = bb + (size_t)row * SEQL + (col & 2047);
                const size_t i1 = i0 + (size_t)8 * SEQL;
                *(uint32_t*)(Ch + i0) = h0; *(uint32_t*)(Cl + i0) = l0;
                *(uint32_t*)(Ch + i1) = h1; *(uint32_t*)(Cl + i1) = l1;
            } else {
                const size_t i0 = (size_t)b * sC + (size_t)row * Nc + col;
                const size_t i1 = (size_t)b * sC + (size_t)(row + 8) * Nc + col;
                *(uint32_t*)(Ch + i0) = pack2(pc[0], pc[1]);
                *(uint32_t*)(Ch + i1) = pack2(pc[2], pc[3]);
            }
        }
}

// ---------------------------------------------------------------------------
// fp32 -> fp16 hi/lo split; up to 4 arrays per launch (blockIdx.y selects)
// ---------------------------------------------------------------------------
struct SplitJob { const float* x; __half* h; __half* l; };

__global__ __launch_bounds__(256)
void split_multi(SplitJob j0, SplitJob j1, SplitJob j2, SplitJob j3, int n4)
{
    const SplitJob& j = (blockIdx.y == 0) ? j0 : (blockIdx.y == 1) ? j1
                      : (blockIdx.y == 2) ? j2 : j3;
    int i = blockIdx.x * 256 + threadIdx.x;
    if (i >= n4) return;
    float4 v = ((const float4*)j.x)[i];
    uint32_t h0, l0, h1, l1;
    split2(v.x, v.y, h0, l0);
    split2(v.z, v.w, h1, l1);
    ((uint2*)j.h)[i] = make_uint2(h0, h1);
    ((uint2*)j.l)[i] = make_uint2(l0, l1);
}

// fp32 -> fp16 convert (hi only); 2 arrays per launch
__global__ __launch_bounds__(256)
void convert2(const float* __restrict__ x0, __half* __restrict__ h0p,
              const float* __restrict__ x1, __half* __restrict__ h1p, int n4)
{
    const float* x = blockIdx.y ? x1 : x0;
    __half* h = blockIdx.y ? h1p : h0p;
    int i = blockIdx.x * 256 + threadIdx.x;
    if (i >= n4) return;
    float4 v = ((const float4*)x)[i];
    ((uint2*)h)[i] = make_uint2(pack2(v.x, v.y), pack2(v.z, v.w));
}

// ---------------------------------------------------------------------------
// masked softmax on fp32 E, writing fp16 (hi only) probabilities
// ---------------------------------------------------------------------------
__global__ __launch_bounds__(256)
void softmax_h(const float* __restrict__ E, const int* __restrict__ mask,
               __half* __restrict__ Ph)
{
    const int row = blockIdx.x;
    const int b = row >> 11;
    const float* e = E + (size_t)row * SEQL;
    const int* m = mask + (size_t)b * SEQL * SEQL + (size_t)(row & 2047) * SEQL;
    const int t = threadIdx.x;
    const int base = t * 8;

    float v[8];
    #pragma unroll
    for (int g = 0; g < 2; g++) {
        float4 ev = *(const float4*)(e + base + g * 4);
        int4 mv = *(const int4*)(m + base + g * 4);
        v[g*4+0] = ((mv.x == 0) ? -1e20f : ev.x) * 0.03125f;
        v[g*4+1] = ((mv.y == 0) ? -1e20f : ev.y) * 0.03125f;
        v[g*4+2] = ((mv.z == 0) ? -1e20f : ev.z) * 0.03125f;
        v[g*4+3] = ((mv.w == 0) ? -1e20f : ev.w) * 0.03125f;
    }
    float mx = -3.4e38f;
    #pragma unroll
    for (int i = 0; i < 8; i++) mx = fmaxf(mx, v[i]);

    __shared__ float red[256];
    red[t] = mx;
    __syncthreads();
    for (int s = 128; s > 0; s >>= 1) {
        if (t < s) red[t] = fmaxf(red[t], red[t + s]);
        __syncthreads();
    }
    mx = red[0];
    __syncthreads();

    float sum = 0.f;
    #pragma unroll
    for (int i = 0; i < 8; i++) { v[i] = __expf(v[i] - mx); sum += v[i]; }
    red[t] = sum;
    __syncthreads();
    for (int s = 128; s > 0; s >>= 1) {
        if (t < s) red[t] += red[t + s];
        __syncthreads();
    }
    const float inv = 1.f / red[0];

    #pragma unroll
    for (int g = 0; g < 2; g++) {
        uint2 hv;
        hv.x = pack2(v[g*4+0] * inv, v[g*4+1] * inv);
        hv.y = pack2(v[g*4+2] * inv, v[g*4+3] * inv);
        ((uint2*)(Ph + (size_t)row * SEQL + base))[g] = hv;
    }
}

// ---------------------------------------------------------------------------
#define SYM(p, s) do { void* _t; cudaGetSymbolAddress(&_t, s); p = (decltype(p))_t; } while (0)

extern "C" void kernel_launch(void* const* d_in, const int* in_sizes, int n_in,
                              void* d_out, int out_size)
{
    const float* values = (const float*)d_in[0];
    const float* keys   = (const float*)d_in[1];
    const float* query  = (const float*)d_in[2];
    const int*   mask   = (const int*)  d_in[3];
    const float* Wv     = (const float*)d_in[4];
    const float* Wk     = (const float*)d_in[5];
    const float* Wq     = (const float*)d_in[6];
    const float* Wo     = (const float*)d_in[7];
    const float* bo     = (const float*)d_in[8];
    float* out = (float*)d_out;

    __half *xvh, *xvl, *xkh, *xqh;
    __half *wvh, *wvl, *wkh, *wkl, *wqh, *wql, *woh, *wol;
    __half *qh, *kh, *kl, *vth, *vtl, *ph, *oh;
    float* ge;
    SYM(xvh, g_xvh); SYM(xvl, g_xvl); SYM(xkh, g_xkh); SYM(xqh, g_xqh);
    SYM(wvh, g_wvh); SYM(wvl, g_wvl); SYM(wkh, g_wkh); SYM(wkl, g_wkl);
    SYM(wqh, g_wqh); SYM(wql, g_wql); SYM(woh, g_woh); SYM(wol, g_wol);
    SYM(qh, g_qh); SYM(kh, g_kh); SYM(kl, g_kl);
    SYM(vth, g_vth); SYM(vtl, g_vtl); SYM(ph, g_ph);
    SYM(oh, g_oh); SYM(ge, g_e);

    cudaFuncSetAttribute(hgemm<0>, cudaFuncAttributeMaxDynamicSharedMemorySize, GEMM_SMEM);
    cudaFuncSetAttribute(hgemm<1>, cudaFuncAttributeMaxDynamicSharedMemorySize, GEMM_SMEM);
    cudaFuncSetAttribute(hgemm<2>, cudaFuncAttributeMaxDynamicSharedMemorySize, GEMM_SMEM);
    cudaFuncSetAttribute(hgemm<3>, cudaFuncAttributeMaxDynamicSharedMemorySize, GEMM_SMEM);
    cudaFuncSetAttribute(hgemm<4>, cudaFuncAttributeMaxDynamicSharedMemorySize, GEMM_SMEM);

    const int n4x = (int)(EX / 4), n4w = (int)(EW / 4);
    {
        SplitJob jv{values, xvh, xvl};
        split_multi<<<dim3((n4x + 255) / 256, 1, 1), 256>>>(jv, jv, jv, jv, n4x);
        SplitJob wv{Wv, wvh, wvl}, wk{Wk, wkh, wkl}, wq{Wq, wqh, wql}, wo{Wo, woh, wol};
        split_multi<<<dim3((n4w + 255) / 256, 4, 1), 256>>>(wv, wk, wq, wo, n4w);
        convert2<<<dim3((n4x + 255) / 256, 2, 1), 256>>>(keys, xkh, query, xqh, n4x);
    }

    // Q = Xq @ Wq^T  (hi-only out; Q lo never used downstream)
    hgemm<4><<<dim3(8, 64, 1), 256, GEMM_SMEM>>>(
        xqh, wqh, wql, EMB, 0, 0, nullptr, nullptr, 0, EMB, qh, nullptr);
    // K = Xk @ Wk^T  (split out)
    hgemm<1><<<dim3(8, 64, 1), 256, GEMM_SMEM>>>(
        xkh, wkh, wkl, EMB, 0, 0, nullptr, nullptr, 0, EMB, kh, kl);
    // Vt = Wv @ Xv^T (split out, batch-folded transposed layout)
    hgemm<3><<<dim3(64, 8, 1), 256, GEMM_SMEM>>>(
        wvh, xvh, xvl, EMB, 0, 0, nullptr, nullptr, 0, SEQL, vth, vtl);

    // E = Qh @ (Kh+Kl)^T per batch (fp32)
    hgemm<0><<<dim3(16, 16, NBAT), 256, GEMM_SMEM>>>(
        qh, kh, kl, EMB, (size_t)SEQL * EMB, (size_t)SEQL * EMB,
        ge, nullptr, (size_t)SEQL * SEQL, SEQL, nullptr, nullptr);

    softmax_h<<<NBAT * SEQL, 256>>>(ge, mask, ph);

    // O = Ph @ (Vth+Vtl)^T per batch (hi-only out)
    hgemm<4><<<dim3(8, 16, NBAT), 256, GEMM_SMEM>>>(
        ph, vth, vtl, SEQL, (size_t)SEQL * SEQL, (size_t)EMB * SEQL,
        nullptr, nullptr, (size_t)SEQL * EMB, EMB, oh, nullptr);

    // out = Oh @ (Woh+Wol)^T + bo (fp32)
    hgemm<2><<<dim3(8, 64, 1), 256, GEMM_SMEM>>>(
        oh, woh, wol, EMB, 0, 0, out, bo, 0, EMB, nullptr, nullptr);
}

// round 10
// speedup vs baseline: 4.3833x; 1.0066x over previous
#include <cuda_runtime.h>
#include <cuda_fp16.h>
#include <cstdint>
#include <cstddef>

// ---------------------------------------------------------------------------
#define NBAT 4
#define SEQL 2048
#define EMB  1024
#define MQ   (NBAT * SEQL)   /* 8192 */

static constexpr size_t EX = (size_t)MQ * EMB;
static constexpr size_t EW = (size_t)EMB * EMB;
static constexpr size_t EP = (size_t)NBAT * SEQL * SEQL;

// Scratch (__device__ statics)
__device__ __half g_xvh[EX], g_xvl[EX];   // values split (B of V-proj)
__device__ __half g_xkh[EX];              // keys hi (A of K-proj)
__device__ __half g_xqh[EX];              // query hi (A of Q-proj)
__device__ __half g_wvh[EW], g_wvl[EW];
__device__ __half g_wkh[EW], g_wkl[EW];
__device__ __half g_wqh[EW], g_wql[EW];
__device__ __half g_woh[EW], g_wol[EW];
__device__ __half g_qh[EX];               // projected Q (hi only)
__device__ __half g_kh[EX],  g_kl[EX];    // projected K split
__device__ __half g_vth[EX], g_vtl[EX];   // projected V split, [b][emb][seq]
__device__ float  g_e[EP];
__device__ __half g_ph[EP];               // softmax probs (hi only)
__device__ __half g_oh[EX];               // attn @ V (hi only)

// ---------------------------------------------------------------------------
__device__ __forceinline__ uint32_t smem_u32(const void* p) {
    uint32_t a;
    asm("{ .reg .u64 t; cvta.to.shared.u64 t, %1; cvt.u32.u64 %0, t; }" : "=r"(a) : "l"(p));
    return a;
}
__device__ __forceinline__ void cp16(uint32_t s, const void* g) {
    asm volatile("cp.async.cg.shared.global [%0], [%1], 16;" :: "r"(s), "l"(g) : "memory");
}
#define CP_COMMIT() asm volatile("cp.async.commit_group;" ::: "memory")

__device__ __forceinline__ void ldsm4(uint32_t* r, uint32_t addr) {
    asm volatile("ldmatrix.sync.aligned.m8n8.x4.shared.b16 {%0,%1,%2,%3}, [%4];"
        : "=r"(r[0]), "=r"(r[1]), "=r"(r[2]), "=r"(r[3]) : "r"(addr));
}
__device__ __forceinline__ void mma16816(float* c, const uint32_t* a, const uint32_t* b) {
    asm volatile("mma.sync.aligned.m16n8k16.row.col.f32.f16.f16.f32 "
        "{%0,%1,%2,%3}, {%4,%5,%6,%7}, {%8,%9}, {%0,%1,%2,%3};"
        : "+f"(c[0]), "+f"(c[1]), "+f"(c[2]), "+f"(c[3])
        : "r"(a[0]), "r"(a[1]), "r"(a[2]), "r"(a[3]), "r"(b[0]), "r"(b[1]));
}

__device__ __forceinline__ void split2(float f0, float f1, uint32_t& hi, uint32_t& lo) {
    __half h0 = __float2half_rn(f0), h1 = __float2half_rn(f1);
    __half l0 = __float2half_rn(f0 - __half2float(h0));
    __half l1 = __float2half_rn(f1 - __half2float(h1));
    hi = (uint32_t)__half_as_ushort(h0) | ((uint32_t)__half_as_ushort(h1) << 16);
    lo = (uint32_t)__half_as_ushort(l0) | ((uint32_t)__half_as_ushort(l1) << 16);
}
__device__ __forceinline__ uint32_t pack2(float f0, float f1) {
    return (uint32_t)__half_as_ushort(__float2half_rn(f0))
         | ((uint32_t)__half_as_ushort(__float2half_rn(f1)) << 16);
}

// ---------------------------------------------------------------------------
// 2-term split HGEMM:  C = Ah*Bh^T + Ah*Bl^T   (fp32 accumulate)
// A,B K-major [rows][K]. CTA tile 128x128, K-chunks of 32.
// 128 threads / 4 warps, warp tile 64x64 -> 128 MMAs per warp per chunk
// against 24 LDSM.x4 (5.3 MMA/LDSM). 3-stage cp.async (wait_group 1),
// 2 CTAs/SM (smem 90KB). smem rows padded to 80B -> conflict-free ldmatrix.
// MODE: 0 fp32 | 1 split fp16 | 2 fp32+bias | 3 split fp16 batch-folded (V)
//       4 fp16 hi-only
// ---------------------------------------------------------------------------
#define TILE_B 10240               /* 128 rows * 80 B */
#define STG_B  (3 * TILE_B)        /* Ah, Bh, Bl */
#define STAGES 3
#define GEMM_SMEM (STAGES * STG_B) /* 92160 */

template <int MODE>
__global__ __launch_bounds__(128, 2)
void hgemm(const __half* __restrict__ Ah,
           const __half* __restrict__ Bh, const __half* __restrict__ Bl,
           int K, size_t sA, size_t sB,
           float* __restrict__ Cf, const float* __restrict__ bias,
           size_t sC, int Nc,
           __half* __restrict__ Ch, __half* __restrict__ Cl)
{
    extern __shared__ char smc[];
    const uint32_t sb = smem_u32(smc);
    const int tid = threadIdx.x, lane = tid & 31, wid = tid >> 5;
    const int m0 = blockIdx.y * 128, n0 = blockIdx.x * 128, b = blockIdx.z;
    const int nch = K >> 5;

    const __half* srcs[3];
    srcs[0] = Ah + (size_t)b * sA + (size_t)m0 * K;
    srcs[1] = Bh + (size_t)b * sB + (size_t)n0 * K;
    srcs[2] = Bl + (size_t)b * sB + (size_t)n0 * K;

    // producer: 1536 cp16 per stage / 128 thr = 12 each
    auto load_stage = [&](int s, int chunk) {
        const uint32_t dbase = sb + s * STG_B;
        const int k0 = chunk * 32;
        #pragma unroll
        for (int i = 0; i < 12; i++) {
            const int cid = tid + i * 128;
            const int tile = cid >> 9, r = (cid >> 2) & 127, seg = cid & 3;
            cp16(dbase + tile * TILE_B + r * 80 + seg * 16,
                 srcs[tile] + (size_t)r * K + k0 + seg * 8);
        }
    };

    load_stage(0, 0);
    CP_COMMIT();
    load_stage(1, 1);
    CP_COMMIT();

    const int m0w = (wid >> 1) * 64, n0w = (wid & 1) * 64;
    const uint32_t aoff = (uint32_t)(m0w + (lane & 15)) * 80 + ((lane >> 4) * 16);
    const uint32_t boff = (uint32_t)(n0w + ((lane >> 4) & 1) * 8 + (lane & 7)) * 80
                        + (((lane >> 3) & 1) * 16);

    float acc[4][8][4];
    #pragma unroll
    for (int a = 0; a < 4; a++)
        #pragma unroll
        for (int c = 0; c < 8; c++)
            #pragma unroll
            for (int d = 0; d < 4; d++) acc[a][c][d] = 0.f;

    for (int c = 0; c < nch; c++) {
        asm volatile("cp.async.wait_group 1;" ::: "memory");
        __syncthreads();
        if (c + 2 < nch) { load_stage((c + 2) % STAGES, c + 2); CP_COMMIT(); }

        const uint32_t st = sb + (c % STAGES) * STG_B;
        const uint32_t aH = st + aoff;
        const uint32_t bH = st + TILE_B + boff, bL = st + 2 * TILE_B + boff;

        #pragma unroll
        for (int ks = 0; ks < 2; ks++) {
            uint32_t ah[4][4], bh[8][2], bl[8][2];
            #pragma unroll
            for (int mi = 0; mi < 4; mi++)
                ldsm4(ah[mi], aH + mi * 1280 + ks * 32);
            #pragma unroll
            for (int j = 0; j < 4; j++) {
                uint32_t t[4];
                ldsm4(t, bH + j * 1280 + ks * 32);
                bh[2*j][0] = t[0]; bh[2*j][1] = t[1];
                bh[2*j+1][0] = t[2]; bh[2*j+1][1] = t[3];
                ldsm4(t, bL + j * 1280 + ks * 32);
                bl[2*j][0] = t[0]; bl[2*j][1] = t[1];
                bl[2*j+1][0] = t[2]; bl[2*j+1][1] = t[3];
            }
            // term-major: 32 independent MMAs, then 32 more
            #pragma unroll
            for (int mi = 0; mi < 4; mi++)
                #pragma unroll
                for (int ni = 0; ni < 8; ni++)
                    mma16816(acc[mi][ni], ah[mi], bh[ni]);
            #pragma unroll
            for (int mi = 0; mi < 4; mi++)
                #pragma unroll
                for (int ni = 0; ni < 8; ni++)
                    mma16816(acc[mi][ni], ah[mi], bl[ni]);
        }
    }

    const int fr = lane >> 2, fc = (lane & 3) * 2;
    #pragma unroll
    for (int mi = 0; mi < 4; mi++)
        #pragma unroll
        for (int ni = 0; ni < 8; ni++) {
            const int row = m0 + m0w + mi * 16 + fr;
            const int col = n0 + n0w + ni * 8 + fc;
            float* pc = acc[mi][ni];
            if (MODE == 0 || MODE == 2) {
                float2 v0 = make_float2(pc[0], pc[1]);
                float2 v1 = make_float2(pc[2], pc[3]);
                if (MODE == 2) {
                    const float b0v = bias[col], b1v = bias[col + 1];
                    v0.x += b0v; v0.y += b1v; v1.x += b0v; v1.y += b1v;
                }
                float* base = Cf + (size_t)b * sC;
                *(float2*)(base + (size_t)row * Nc + col) = v0;
                *(float2*)(base + (size_t)(row + 8) * Nc + col) = v1;
            } else if (MODE == 1) {
                uint32_t h0, l0, h1, l1;
                split2(pc[0], pc[1], h0, l0);
                split2(pc[2], pc[3], h1, l1);
                const size_t i0 = (size_t)b * sC + (size_t)row * Nc + col;
                const size_t i1 = (size_t)b * sC + (size_t)(row + 8) * Nc + col;
                *(uint32_t*)(Ch + i0) = h0; *(uint32_t*)(Cl + i0) = l0;
                *(uint32_t*)(Ch + i1) = h1; *(uint32_t*)(Cl + i1) = l1;
            } else if (MODE == 3) {
                uint32_t h0, l0, h1, l1;
                split2(pc[0], pc[1], h0, l0);
                split2(pc[2], pc[3], h1, l1);
                const size_t bb = (size_t)(col >> 11) * ((size_t)EMB * SEQL);
                const size_t i0 = bb + (size_t)row * SEQL + (col & 2047);
                const size_t i1 = i0 + (size_t)8 * SEQL;
                *(uint32_t*)(Ch + i0) = h0; *(uint32_t*)(Cl + i0) = l0;
                *(uint32_t*)(Ch + i1) = h1; *(uint32_t*)(Cl + i1) = l1;
            } else {
                const size_t i0 = (size_t)b * sC + (size_t)row * Nc + col;
                const size_t i1 = (size_t)b * sC + (size_t)(row + 8) * Nc + col;
                *(uint32_t*)(Ch + i0) = pack2(pc[0], pc[1]);
                *(uint32_t*)(Ch + i1) = pack2(pc[2], pc[3]);
            }
        }
}

// ---------------------------------------------------------------------------
// fp32 -> fp16 hi/lo split; up to 4 arrays per launch (blockIdx.y selects)
// ---------------------------------------------------------------------------
struct SplitJob { const float* x; __half* h; __half* l; };

__global__ __launch_bounds__(256)
void split_multi(SplitJob j0, SplitJob j1, SplitJob j2, SplitJob j3, int n4)
{
    const SplitJob& j = (blockIdx.y == 0) ? j0 : (blockIdx.y == 1) ? j1
                      : (blockIdx.y == 2) ? j2 : j3;
    int i = blockIdx.x * 256 + threadIdx.x;
    if (i >= n4) return;
    float4 v = ((const float4*)j.x)[i];
    uint32_t h0, l0, h1, l1;
    split2(v.x, v.y, h0, l0);
    split2(v.z, v.w, h1, l1);
    ((uint2*)j.h)[i] = make_uint2(h0, h1);
    ((uint2*)j.l)[i] = make_uint2(l0, l1);
}

// fp32 -> fp16 convert (hi only); 2 arrays per launch
__global__ __launch_bounds__(256)
void convert2(const float* __restrict__ x0, __half* __restrict__ h0p,
              const float* __restrict__ x1, __half* __restrict__ h1p, int n4)
{
    const float* x = blockIdx.y ? x1 : x0;
    __half* h = blockIdx.y ? h1p : h0p;
    int i = blockIdx.x * 256 + threadIdx.x;
    if (i >= n4) return;
    float4 v = ((const float4*)x)[i];
    ((uint2*)h)[i] = make_uint2(pack2(v.x, v.y), pack2(v.z, v.w));
}

// ---------------------------------------------------------------------------
// masked softmax on fp32 E, writing fp16 (hi only) probabilities
// ---------------------------------------------------------------------------
__global__ __launch_bounds__(256)
void softmax_h(const float* __restrict__ E, const int* __restrict__ mask,
               __half* __restrict__ Ph)
{
    const int row = blockIdx.x;
    const int b = row >> 11;
    const float* e = E + (size_t)row * SEQL;
    const int* m = mask + (size_t)b * SEQL * SEQL + (size_t)(row & 2047) * SEQL;
    const int t = threadIdx.x;
    const int base = t * 8;

    float v[8];
    #pragma unroll
    for (int g = 0; g < 2; g++) {
        float4 ev = *(const float4*)(e + base + g * 4);
        int4 mv = *(const int4*)(m + base + g * 4);
        v[g*4+0] = ((mv.x == 0) ? -1e20f : ev.x) * 0.03125f;
        v[g*4+1] = ((mv.y == 0) ? -1e20f : ev.y) * 0.03125f;
        v[g*4+2] = ((mv.z == 0) ? -1e20f : ev.z) * 0.03125f;
        v[g*4+3] = ((mv.w == 0) ? -1e20f : ev.w) * 0.03125f;
    }
    float mx = -3.4e38f;
    #pragma unroll
    for (int i = 0; i < 8; i++) mx = fmaxf(mx, v[i]);

    __shared__ float red[256];
    red[t] = mx;
    __syncthreads();
    for (int s = 128; s > 0; s >>= 1) {
        if (t < s) red[t] = fmaxf(red[t], red[t + s]);
        __syncthreads();
    }
    mx = red[0];
    __syncthreads();

    float sum = 0.f;
    #pragma unroll
    for (int i = 0; i < 8; i++) { v[i] = __expf(v[i] - mx); sum += v[i]; }
    red[t] = sum;
    __syncthreads();
    for (int s = 128; s > 0; s >>= 1) {
        if (t < s) red[t] += red[t + s];
        __syncthreads();
    }
    const float inv = 1.f / red[0];

    #pragma unroll
    for (int g = 0; g < 2; g++) {
        uint2 hv;
        hv.x = pack2(v[g*4+0] * inv, v[g*4+1] * inv);
        hv.y = pack2(v[g*4+2] * inv, v[g*4+3] * inv);
        ((uint2*)(Ph + (size_t)row * SEQL + base))[g] = hv;
    }
}

// ---------------------------------------------------------------------------
#define SYM(p, s) do { void* _t; cudaGetSymbolAddress(&_t, s); p = (decltype(p))_t; } while (0)

extern "C" void kernel_launch(void* const* d_in, const int* in_sizes, int n_in,
                              void* d_out, int out_size)
{
    const float* values = (const float*)d_in[0];
    const float* keys   = (const float*)d_in[1];
    const float* query  = (const float*)d_in[2];
    const int*   mask   = (const int*)  d_in[3];
    const float* Wv     = (const float*)d_in[4];
    const float* Wk     = (const float*)d_in[5];
    const float* Wq     = (const float*)d_in[6];
    const float* Wo     = (const float*)d_in[7];
    const float* bo     = (const float*)d_in[8];
    float* out = (float*)d_out;

    __half *xvh, *xvl, *xkh, *xqh;
    __half *wvh, *wvl, *wkh, *wkl, *wqh, *wql, *woh, *wol;
    __half *qh, *kh, *kl, *vth, *vtl, *ph, *oh;
    float* ge;
    SYM(xvh, g_xvh); SYM(xvl, g_xvl); SYM(xkh, g_xkh); SYM(xqh, g_xqh);
    SYM(wvh, g_wvh); SYM(wvl, g_wvl); SYM(wkh, g_wkh); SYM(wkl, g_wkl);
    SYM(wqh, g_wqh); SYM(wql, g_wql); SYM(woh, g_woh); SYM(wol, g_wol);
    SYM(qh, g_qh); SYM(kh, g_kh); SYM(kl, g_kl);
    SYM(vth, g_vth); SYM(vtl, g_vtl); SYM(ph, g_ph);
    SYM(oh, g_oh); SYM(ge, g_e);

    cudaFuncSetAttribute(hgemm<0>, cudaFuncAttributeMaxDynamicSharedMemorySize, GEMM_SMEM);
    cudaFuncSetAttribute(hgemm<1>, cudaFuncAttributeMaxDynamicSharedMemorySize, GEMM_SMEM);
    cudaFuncSetAttribute(hgemm<2>, cudaFuncAttributeMaxDynamicSharedMemorySize, GEMM_SMEM);
    cudaFuncSetAttribute(hgemm<3>, cudaFuncAttributeMaxDynamicSharedMemorySize, GEMM_SMEM);
    cudaFuncSetAttribute(hgemm<4>, cudaFuncAttributeMaxDynamicSharedMemorySize, GEMM_SMEM);

    const int n4x = (int)(EX / 4), n4w = (int)(EW / 4);
    {
        SplitJob jv{values, xvh, xvl};
        split_multi<<<dim3((n4x + 255) / 256, 1, 1), 256>>>(jv, jv, jv, jv, n4x);
        SplitJob wv{Wv, wvh, wvl}, wk{Wk, wkh, wkl}, wq{Wq, wqh, wql}, wo{Wo, woh, wol};
        split_multi<<<dim3((n4w + 255) / 256, 4, 1), 256>>>(wv, wk, wq, wo, n4w);
        convert2<<<dim3((n4x + 255) / 256, 2, 1), 256>>>(keys, xkh, query, xqh, n4x);
    }

    // Q = Xq @ Wq^T  (hi-only out)
    hgemm<4><<<dim3(8, 64, 1), 128, GEMM_SMEM>>>(
        xqh, wqh, wql, EMB, 0, 0, nullptr, nullptr, 0, EMB, qh, nullptr);
    // K = Xk @ Wk^T  (split out)
    hgemm<1><<<dim3(8, 64, 1), 128, GEMM_SMEM>>>(
        xkh, wkh, wkl, EMB, 0, 0, nullptr, nullptr, 0, EMB, kh, kl);
    // Vt = Wv @ Xv^T (split out, batch-folded transposed layout)
    hgemm<3><<<dim3(64, 8, 1), 128, GEMM_SMEM>>>(
        wvh, xvh, xvl, EMB, 0, 0, nullptr, nullptr, 0, SEQL, vth, vtl);

    // E = Qh @ (Kh+Kl)^T per batch (fp32)
    hgemm<0><<<dim3(16, 16, NBAT), 128, GEMM_SMEM>>>(
        qh, kh, kl, EMB, (size_t)SEQL * EMB, (size_t)SEQL * EMB,
        ge, nullptr, (size_t)SEQL * SEQL, SEQL, nullptr, nullptr);

    softmax_h<<<NBAT * SEQL, 256>>>(ge, mask, ph);

    // O = Ph @ (Vth+Vtl)^T per batch (hi-only out)
    hgemm<4><<<dim3(8, 16, NBAT), 128, GEMM_SMEM>>>(
        ph, vth, vtl, SEQL, (size_t)SEQL * SEQL, (size_t)EMB * SEQL,
        nullptr, nullptr, (size_t)SEQL * EMB, EMB, oh, nullptr);

    // out = Oh @ (Woh+Wol)^T + bo (fp32)
    hgemm<2><<<dim3(8, 64, 1), 128, GEMM_SMEM>>>(
        oh, woh, wol, EMB, 0, 0, out, bo, 0, EMB, nullptr, nullptr);
}